// round 1
// baseline (speedup 1.0000x reference)
#include <cuda_runtime.h>
#include <cstdint>

#define B_   2
#define S_   2048
#define D_   1024
#define H_   16
#define DK_  64
#define BH_  (B_ * H_)
#define M_ROWS (B_ * S_)   // 4096

// scratch (static device globals; no allocation allowed)
__device__ float g_Q[BH_ * S_ * DK_];
__device__ float g_K[BH_ * S_ * DK_];
__device__ float g_V[BH_ * S_ * DK_];
__device__ float g_ctx[B_ * S_ * D_];

// ---------------------------------------------------------------------------
// GEMM: Y = X @ W + bias.  M x N x K, all multiples of (128,128,8).
// mode 0: Y row-major [M,N].  mode 1: scatter into [B,H,S,DK] head layout.
// 256 threads, 128x128 block tile, 8x8 per-thread microtile, BK=8.
// ---------------------------------------------------------------------------
__global__ __launch_bounds__(256) void gemm_bias(
    const float* __restrict__ X, const float* __restrict__ W,
    const float* __restrict__ bias, float* __restrict__ Y,
    int M, int N, int K, int mode)
{
    __shared__ float Xs[8][132];   // [k][m], padded vs bank conflicts
    __shared__ float Ws[8][128];   // [k][n]

    const int tid = threadIdx.x;
    const int tr  = tid >> 4;      // 0..15 -> 8 rows each
    const int tc  = tid & 15;      // 0..15 -> 8 cols each
    const int bm  = blockIdx.y * 128;
    const int bn  = blockIdx.x * 128;

    float acc[8][8];
#pragma unroll
    for (int i = 0; i < 8; i++)
#pragma unroll
        for (int j = 0; j < 8; j++) acc[i][j] = 0.f;

    const int lxr = tid >> 1;            // 0..127 X row
    const int lxs = (tid & 1) * 4;       // k-segment 0 or 4
    const int lwk = tid >> 5;            // 0..7 W k-row
    const int lwn = (tid & 31) * 4;      // n offset

    const float* Xg = X + (size_t)(bm + lxr) * K + lxs;
    const float* Wg = W + (size_t)lwk * N + bn + lwn;

    for (int k0 = 0; k0 < K; k0 += 8) {
        float4 xv = *(const float4*)(Xg + k0);
        Xs[lxs + 0][lxr] = xv.x;
        Xs[lxs + 1][lxr] = xv.y;
        Xs[lxs + 2][lxr] = xv.z;
        Xs[lxs + 3][lxr] = xv.w;
        *(float4*)&Ws[lwk][lwn] = *(const float4*)(Wg + (size_t)k0 * N);
        __syncthreads();

#pragma unroll
        for (int kk = 0; kk < 8; kk++) {
            float a[8], b[8];
            *(float4*)&a[0] = *(float4*)&Xs[kk][tr * 8];
            *(float4*)&a[4] = *(float4*)&Xs[kk][tr * 8 + 4];
            *(float4*)&b[0] = *(float4*)&Ws[kk][tc * 8];
            *(float4*)&b[4] = *(float4*)&Ws[kk][tc * 8 + 4];
#pragma unroll
            for (int i = 0; i < 8; i++)
#pragma unroll
                for (int j = 0; j < 8; j++)
                    acc[i][j] = fmaf(a[i], b[j], acc[i][j]);
        }
        __syncthreads();
    }

#pragma unroll
    for (int i = 0; i < 8; i++) {
        const int m = bm + tr * 8 + i;
#pragma unroll
        for (int j = 0; j < 8; j++) {
            const int n = bn + tc * 8 + j;
            const float v = acc[i][j] + bias[n];
            if (mode == 0) {
                Y[(size_t)m * N + n] = v;
            } else {
                const int b  = m >> 11;        // m / 2048
                const int s  = m & 2047;
                const int h  = n >> 6;         // n / 64
                const int dk = n & 63;
                Y[(((size_t)(b * H_ + h)) * S_ + s) * DK_ + dk] = v;
            }
        }
    }
}

// ---------------------------------------------------------------------------
// Flash attention (causal), fp32, online softmax.
// Block: 64 q-rows of one (b,h); loops over 64-key tiles up to the diagonal.
// 256 threads; thread (tr,tc) owns 4 rows x 4 cols of scores / 4x4 of output.
// smem: Qs_t[d][row], Ks_t[d][col], Vs[k][d], Ps[row][col]; stride 68 pad.
// ---------------------------------------------------------------------------
#define PADW 68
#define SM_TILE (64 * PADW)

__global__ __launch_bounds__(256) void flash_attn(
    const float* __restrict__ Q, const float* __restrict__ K,
    const float* __restrict__ V, float* __restrict__ O)
{
    extern __shared__ float sm[];
    float* Qs = sm;                 // [d * PADW + row], pre-scaled by 1/8
    float* Ks = sm + SM_TILE;       // [d * PADW + col]
    float* Vs = sm + 2 * SM_TILE;   // [k * PADW + d]
    float* Ps = sm + 3 * SM_TILE;   // [row * PADW + col]

    const int tid = threadIdx.x;
    const int tr  = tid >> 4;   // 0..15
    const int tc  = tid & 15;   // 0..15
    const int qt  = gridDim.x - 1 - blockIdx.x;   // heavy tiles first
    const int bh  = blockIdx.y;

    const float* Qp = Q + ((size_t)bh * S_ + (size_t)qt * 64) * DK_;
    const float* Kp = K + (size_t)bh * S_ * DK_;
    const float* Vp = V + (size_t)bh * S_ * DK_;

    // load + scale Q tile (transposed into smem)
    for (int idx = tid; idx < 64 * 64; idx += 256) {
        const int r = idx >> 6, d = idx & 63;
        Qs[d * PADW + r] = Qp[idx] * 0.125f;   // 1/sqrt(64)
    }

    float m_i[4], l_i[4], acc[4][4];
#pragma unroll
    for (int i = 0; i < 4; i++) {
        m_i[i] = -1e30f; l_i[i] = 0.f;
#pragma unroll
        for (int j = 0; j < 4; j++) acc[i][j] = 0.f;
    }

    for (int jt = 0; jt <= qt; jt++) {
        const float* Kt = Kp + (size_t)jt * 64 * DK_;
        const float* Vt = Vp + (size_t)jt * 64 * DK_;

        __syncthreads();   // Q visible (iter 0); prev PV done before reload
        for (int idx = tid; idx < 64 * 64; idx += 256) {
            const int r = idx >> 6, d = idx & 63;
            Ks[d * PADW + r] = Kt[idx];
            Vs[r * PADW + d] = Vt[idx];
        }
        __syncthreads();

        // scores: S = (Q/8) @ K^T
        float s[4][4];
#pragma unroll
        for (int i = 0; i < 4; i++)
#pragma unroll
            for (int j = 0; j < 4; j++) s[i][j] = 0.f;

#pragma unroll 4
        for (int d = 0; d < 64; d++) {
            const float4 a = *(const float4*)&Qs[d * PADW + tr * 4];
            const float4 b = *(const float4*)&Ks[d * PADW + tc * 4];
            s[0][0] = fmaf(a.x, b.x, s[0][0]); s[0][1] = fmaf(a.x, b.y, s[0][1]);
            s[0][2] = fmaf(a.x, b.z, s[0][2]); s[0][3] = fmaf(a.x, b.w, s[0][3]);
            s[1][0] = fmaf(a.y, b.x, s[1][0]); s[1][1] = fmaf(a.y, b.y, s[1][1]);
            s[1][2] = fmaf(a.y, b.z, s[1][2]); s[1][3] = fmaf(a.y, b.w, s[1][3]);
            s[2][0] = fmaf(a.z, b.x, s[2][0]); s[2][1] = fmaf(a.z, b.y, s[2][1]);
            s[2][2] = fmaf(a.z, b.z, s[2][2]); s[2][3] = fmaf(a.z, b.w, s[2][3]);
            s[3][0] = fmaf(a.w, b.x, s[3][0]); s[3][1] = fmaf(a.w, b.y, s[3][1]);
            s[3][2] = fmaf(a.w, b.z, s[3][2]); s[3][3] = fmaf(a.w, b.w, s[3][3]);
        }

        if (jt == qt) {   // diagonal tile: causal mask (matches ref -1e9)
#pragma unroll
            for (int i = 0; i < 4; i++)
#pragma unroll
                for (int j = 0; j < 4; j++)
                    if (tc * 4 + j > tr * 4 + i) s[i][j] = -1e9f;
        }

        // online softmax update + store P
#pragma unroll
        for (int i = 0; i < 4; i++) {
            float mt = fmaxf(fmaxf(s[i][0], s[i][1]), fmaxf(s[i][2], s[i][3]));
#pragma unroll
            for (int off = 1; off < 16; off <<= 1)
                mt = fmaxf(mt, __shfl_xor_sync(0xffffffffu, mt, off));
            const float mn = fmaxf(m_i[i], mt);
            const float al = __expf(m_i[i] - mn);
            float rs = 0.f;
#pragma unroll
            for (int j = 0; j < 4; j++) {
                s[i][j] = __expf(s[i][j] - mn);
                rs += s[i][j];
            }
#pragma unroll
            for (int off = 1; off < 16; off <<= 1)
                rs += __shfl_xor_sync(0xffffffffu, rs, off);
            l_i[i] = l_i[i] * al + rs;
            m_i[i] = mn;
#pragma unroll
            for (int j = 0; j < 4; j++) acc[i][j] *= al;
            *(float4*)&Ps[(tr * 4 + i) * PADW + tc * 4] =
                make_float4(s[i][0], s[i][1], s[i][2], s[i][3]);
        }
        __syncthreads();

        // acc += P @ V
#pragma unroll 4
        for (int k4 = 0; k4 < 64; k4 += 4) {
            float4 pr[4];
#pragma unroll
            for (int i = 0; i < 4; i++)
                pr[i] = *(const float4*)&Ps[(tr * 4 + i) * PADW + k4];
#pragma unroll
            for (int kk = 0; kk < 4; kk++) {
                const float4 v = *(const float4*)&Vs[(k4 + kk) * PADW + tc * 4];
                const float p0 = (kk == 0) ? pr[0].x : (kk == 1) ? pr[0].y : (kk == 2) ? pr[0].z : pr[0].w;
                const float p1 = (kk == 0) ? pr[1].x : (kk == 1) ? pr[1].y : (kk == 2) ? pr[1].z : pr[1].w;
                const float p2 = (kk == 0) ? pr[2].x : (kk == 1) ? pr[2].y : (kk == 2) ? pr[2].z : pr[2].w;
                const float p3 = (kk == 0) ? pr[3].x : (kk == 1) ? pr[3].y : (kk == 2) ? pr[3].z : pr[3].w;
                acc[0][0] = fmaf(p0, v.x, acc[0][0]); acc[0][1] = fmaf(p0, v.y, acc[0][1]);
                acc[0][2] = fmaf(p0, v.z, acc[0][2]); acc[0][3] = fmaf(p0, v.w, acc[0][3]);
                acc[1][0] = fmaf(p1, v.x, acc[1][0]); acc[1][1] = fmaf(p1, v.y, acc[1][1]);
                acc[1][2] = fmaf(p1, v.z, acc[1][2]); acc[1][3] = fmaf(p1, v.w, acc[1][3]);
                acc[2][0] = fmaf(p2, v.x, acc[2][0]); acc[2][1] = fmaf(p2, v.y, acc[2][1]);
                acc[2][2] = fmaf(p2, v.z, acc[2][2]); acc[2][3] = fmaf(p2, v.w, acc[2][3]);
                acc[3][0] = fmaf(p3, v.x, acc[3][0]); acc[3][1] = fmaf(p3, v.y, acc[3][1]);
                acc[3][2] = fmaf(p3, v.z, acc[3][2]); acc[3][3] = fmaf(p3, v.w, acc[3][3]);
            }
        }
    }

    // epilogue: ctx[b, q, h*64 + d] = acc / l
    const int b = bh >> 4, h = bh & 15;
#pragma unroll
    for (int i = 0; i < 4; i++) {
        const float inv = 1.f / l_i[i];
        const int r = qt * 64 + tr * 4 + i;
#pragma unroll
        for (int j = 0; j < 4; j++)
            O[((size_t)(b * S_ + r)) * D_ + h * 64 + tc * 4 + j] = acc[i][j] * inv;
    }
}

// ---------------------------------------------------------------------------
extern "C" void kernel_launch(void* const* d_in, const int* in_sizes, int n_in,
                              void* d_out, int out_size)
{
    const float* x  = (const float*)d_in[0];
    // d_in[1] = mask (tril by construction) -> causal handled in-kernel
    const float* Wq = (const float*)d_in[2];
    const float* bq = (const float*)d_in[3];
    const float* Wk = (const float*)d_in[4];
    const float* bk = (const float*)d_in[5];
    const float* Wv = (const float*)d_in[6];
    const float* bv = (const float*)d_in[7];
    const float* Wo = (const float*)d_in[8];
    const float* bo = (const float*)d_in[9];

    float *qb, *kb, *vb, *cb;
    cudaGetSymbolAddress((void**)&qb, g_Q);
    cudaGetSymbolAddress((void**)&kb, g_K);
    cudaGetSymbolAddress((void**)&vb, g_V);
    cudaGetSymbolAddress((void**)&cb, g_ctx);

    const dim3 gg(D_ / 128, M_ROWS / 128);   // (8, 32)
    gemm_bias<<<gg, 256>>>(x, Wq, bq, qb, M_ROWS, D_, D_, 1);
    gemm_bias<<<gg, 256>>>(x, Wk, bk, kb, M_ROWS, D_, D_, 1);
    gemm_bias<<<gg, 256>>>(x, Wv, bv, vb, M_ROWS, D_, D_, 1);

    const int smem = 4 * SM_TILE * sizeof(float);   // 69632 B
    cudaFuncSetAttribute(flash_attn, cudaFuncAttributeMaxDynamicSharedMemorySize, smem);
    const dim3 ga(S_ / 64, BH_);   // (32, 32)
    flash_attn<<<ga, 256, smem>>>(qb, kb, vb, cb);

    gemm_bias<<<gg, 256>>>(cb, Wo, bo, (float*)d_out, M_ROWS, D_, D_, 0);
}

// round 3
// speedup vs baseline: 1.7317x; 1.7317x over previous
#include <cuda_runtime.h>
#include <cuda_bf16.h>
#include <cstdint>

#define B_   2
#define S_   2048
#define D_   1024
#define H_   16
#define DK_  64
#define BH_  (B_ * H_)
#define M_ROWS (B_ * S_)   // 4096

// ---------------- scratch (static device globals) ----------------
__device__ float g_Q[BH_ * S_ * DK_];
__device__ float g_K[BH_ * S_ * DK_];
__device__ float g_V[BH_ * S_ * DK_];
__device__ float g_ctx[B_ * S_ * D_];
__device__ __nv_bfloat16 g_Xhi[M_ROWS * D_];
__device__ __nv_bfloat16 g_Xlo[M_ROWS * D_];
__device__ __nv_bfloat16 g_Wth[D_ * D_];
__device__ __nv_bfloat16 g_Wtl[D_ * D_];

// ---------------- helpers ----------------
__device__ __forceinline__ uint32_t smem_u32(const void* p) {
    uint32_t a;
    asm("{ .reg .u64 t; cvta.to.shared.u64 t, %1; cvt.u32.u64 %0, t; }" : "=r"(a) : "l"(p));
    return a;
}
__device__ __forceinline__ void ldsm4(uint32_t* r, uint32_t addr) {
    asm volatile("ldmatrix.sync.aligned.m8n8.x4.shared.b16 {%0,%1,%2,%3}, [%4];"
        : "=r"(r[0]), "=r"(r[1]), "=r"(r[2]), "=r"(r[3]) : "r"(addr));
}
__device__ __forceinline__ void ldsm2(uint32_t* r, uint32_t addr) {
    asm volatile("ldmatrix.sync.aligned.m8n8.x2.shared.b16 {%0,%1}, [%2];"
        : "=r"(r[0]), "=r"(r[1]) : "r"(addr));
}
__device__ __forceinline__ void mma16816(float* c, const uint32_t* a, const uint32_t* b) {
    asm volatile("mma.sync.aligned.m16n8k16.row.col.f32.bf16.bf16.f32 "
        "{%0,%1,%2,%3}, {%4,%5,%6,%7}, {%8,%9}, {%0,%1,%2,%3};"
        : "+f"(c[0]), "+f"(c[1]), "+f"(c[2]), "+f"(c[3])
        : "r"(a[0]), "r"(a[1]), "r"(a[2]), "r"(a[3]), "r"(b[0]), "r"(b[1]));
}

// ---------------------------------------------------------------------------
// split fp32 -> bf16 hi/lo pair
// ---------------------------------------------------------------------------
__global__ __launch_bounds__(256) void split_bf16(
    const float* __restrict__ src, __nv_bfloat16* __restrict__ hi,
    __nv_bfloat16* __restrict__ lo, int n4)
{
    int i = blockIdx.x * blockDim.x + threadIdx.x;
    if (i >= n4) return;
    float4 v = ((const float4*)src)[i];
    __nv_bfloat16 h0 = __float2bfloat16(v.x), h1 = __float2bfloat16(v.y);
    __nv_bfloat16 h2 = __float2bfloat16(v.z), h3 = __float2bfloat16(v.w);
    __nv_bfloat16 l0 = __float2bfloat16(v.x - __bfloat162float(h0));
    __nv_bfloat16 l1 = __float2bfloat16(v.y - __bfloat162float(h1));
    __nv_bfloat16 l2 = __float2bfloat16(v.z - __bfloat162float(h2));
    __nv_bfloat16 l3 = __float2bfloat16(v.w - __bfloat162float(h3));
    __nv_bfloat162 hp0 = {h0, h1}, hp1 = {h2, h3}, lp0 = {l0, l1}, lp1 = {l2, l3};
    uint2 hu, lu;
    hu.x = *(uint32_t*)&hp0; hu.y = *(uint32_t*)&hp1;
    lu.x = *(uint32_t*)&lp0; lu.y = *(uint32_t*)&lp1;
    ((uint2*)hi)[i] = hu;
    ((uint2*)lo)[i] = lu;
}

// ---------------------------------------------------------------------------
// transpose W [K,N] -> Wt [N,K] with bf16 hi/lo split (1024x1024)
// ---------------------------------------------------------------------------
__global__ void transpose_split(const float* __restrict__ W,
                                __nv_bfloat16* __restrict__ hi,
                                __nv_bfloat16* __restrict__ lo)
{
    __shared__ float t[32][33];
    const int k = blockIdx.y * 32 + threadIdx.y;
    const int n = blockIdx.x * 32 + threadIdx.x;
    t[threadIdx.y][threadIdx.x] = W[(size_t)k * D_ + n];
    __syncthreads();
    const int nn = blockIdx.x * 32 + threadIdx.y;
    const int kk = blockIdx.y * 32 + threadIdx.x;
    float v = t[threadIdx.x][threadIdx.y];
    __nv_bfloat16 h = __float2bfloat16(v);
    __nv_bfloat16 l = __float2bfloat16(v - __bfloat162float(h));
    hi[(size_t)nn * D_ + kk] = h;
    lo[(size_t)nn * D_ + kk] = l;
}

// ---------------------------------------------------------------------------
// HMMA GEMM: Y[M,N] = A[M,K] @ Bt[N,K]^T + bias, 3x bf16-split mma.sync.
// M=4096, N=1024, K=1024. CTA: 128x128 tile, 8 warps (2Mx4N), BK=32.
// smem rows padded to 80B for conflict-free ldmatrix.
// mode 0: row-major out. mode 1: scatter to [B,H,S,DK].
// ---------------------------------------------------------------------------
#define ROWB 80   // bytes per padded smem row (32 bf16 + 8 pad)
#define TILEB (128 * ROWB)

__global__ __launch_bounds__(256, 1) void gemm_tc(
    const __nv_bfloat16* __restrict__ Ah, const __nv_bfloat16* __restrict__ Al,
    const __nv_bfloat16* __restrict__ Bh, const __nv_bfloat16* __restrict__ Bl,
    const float* __restrict__ bias, float* __restrict__ Y, int mode)
{
    __shared__ __align__(16) unsigned char smc[4 * TILEB];
    const uint32_t s0  = smem_u32(smc);
    const uint32_t SAh = s0, SAl = s0 + TILEB, SBh = s0 + 2 * TILEB, SBl = s0 + 3 * TILEB;

    const int tid = threadIdx.x, wid = tid >> 5, lane = tid & 31;
    const int wm = wid >> 2, wn = wid & 3;            // warp grid 2x4
    const int bm = blockIdx.y * 128, bn = blockIdx.x * 128;

    // -- global load geometry: each thread: 1 row, 32B (2x uint4) per tile --
    const int lrow = tid >> 1;
    const int lcol = (tid & 1) * 16;
    const __nv_bfloat16* gAh = Ah + (size_t)(bm + lrow) * 1024 + lcol;
    const __nv_bfloat16* gAl = Al + (size_t)(bm + lrow) * 1024 + lcol;
    const __nv_bfloat16* gBh = Bh + (size_t)(bn + lrow) * 1024 + lcol;
    const __nv_bfloat16* gBl = Bl + (size_t)(bn + lrow) * 1024 + lcol;
    const uint32_t sts = (uint32_t)lrow * ROWB + (uint32_t)(tid & 1) * 32;

    // -- ldmatrix lane addressing --
    const uint32_t a_off = (uint32_t)(lane & 15) * ROWB + (uint32_t)(lane >> 4) * 16;
    const uint32_t b_off = (uint32_t)(lane & 7) * ROWB + (uint32_t)((lane >> 3) & 1) * 16;
    const uint32_t aBase = (uint32_t)(wm * 64) * ROWB + a_off;
    const uint32_t bBase = (uint32_t)(wn * 32) * ROWB + b_off;

    float acc[16][4];
#pragma unroll
    for (int i = 0; i < 16; i++)
#pragma unroll
        for (int j = 0; j < 4; j++) acc[i][j] = 0.f;

    uint4 pre[8];
#pragma unroll
    for (int t = 0; t < 2; t++) {
        pre[0 + t] = *(const uint4*)(gAh + t * 8);
        pre[2 + t] = *(const uint4*)(gAl + t * 8);
        pre[4 + t] = *(const uint4*)(gBh + t * 8);
        pre[6 + t] = *(const uint4*)(gBl + t * 8);
    }

    for (int ks = 0; ks < 32; ks++) {
        *(uint4*)(smc + 0 * TILEB + sts)      = pre[0];
        *(uint4*)(smc + 0 * TILEB + sts + 16) = pre[1];
        *(uint4*)(smc + 1 * TILEB + sts)      = pre[2];
        *(uint4*)(smc + 1 * TILEB + sts + 16) = pre[3];
        *(uint4*)(smc + 2 * TILEB + sts)      = pre[4];
        *(uint4*)(smc + 2 * TILEB + sts + 16) = pre[5];
        *(uint4*)(smc + 3 * TILEB + sts)      = pre[6];
        *(uint4*)(smc + 3 * TILEB + sts + 16) = pre[7];
        __syncthreads();

        if (ks < 31) {
            const int ko = (ks + 1) * 32;
#pragma unroll
            for (int t = 0; t < 2; t++) {
                pre[0 + t] = *(const uint4*)(gAh + ko + t * 8);
                pre[2 + t] = *(const uint4*)(gAl + ko + t * 8);
                pre[4 + t] = *(const uint4*)(gBh + ko + t * 8);
                pre[6 + t] = *(const uint4*)(gBl + ko + t * 8);
            }
        }

#pragma unroll
        for (int h = 0; h < 2; h++) {
            uint32_t fAh[4][4], fAl[4][4], fB[4][2];
#pragma unroll
            for (int mt = 0; mt < 4; mt++) {
                const uint32_t ra = aBase + (uint32_t)(mt * 16) * ROWB + (uint32_t)h * 32;
                ldsm4(fAh[mt], SAh + ra);
                ldsm4(fAl[mt], SAl + ra);
            }
#pragma unroll
            for (int nt = 0; nt < 4; nt++)
                ldsm2(fB[nt], SBh + bBase + (uint32_t)(nt * 8) * ROWB + (uint32_t)h * 32);
#pragma unroll
            for (int mt = 0; mt < 4; mt++)
#pragma unroll
                for (int nt = 0; nt < 4; nt++) {
                    mma16816(acc[mt * 4 + nt], fAh[mt], fB[nt]);
                    mma16816(acc[mt * 4 + nt], fAl[mt], fB[nt]);
                }
#pragma unroll
            for (int nt = 0; nt < 4; nt++)
                ldsm2(fB[nt], SBl + bBase + (uint32_t)(nt * 8) * ROWB + (uint32_t)h * 32);
#pragma unroll
            for (int mt = 0; mt < 4; mt++)
#pragma unroll
                for (int nt = 0; nt < 4; nt++)
                    mma16816(acc[mt * 4 + nt], fAh[mt], fB[nt]);
        }
        __syncthreads();
    }

    // -- epilogue --
    const int qr = lane >> 2, qc = (lane & 3) * 2;
#pragma unroll
    for (int mt = 0; mt < 4; mt++) {
#pragma unroll
        for (int nt = 0; nt < 4; nt++) {
            const float* a4 = acc[mt * 4 + nt];
            const int r0 = bm + wm * 64 + mt * 16 + qr;
            const int cn = bn + wn * 32 + nt * 8 + qc;
            const float b0 = bias[cn], b1 = bias[cn + 1];
            float2 v0 = {a4[0] + b0, a4[1] + b1};
            float2 v1 = {a4[2] + b0, a4[3] + b1};
            if (mode == 0) {
                *(float2*)(Y + (size_t)r0 * 1024 + cn) = v0;
                *(float2*)(Y + (size_t)(r0 + 8) * 1024 + cn) = v1;
            } else {
                const int h  = cn >> 6, dk = cn & 63;
                const int b0i = r0 >> 11, s0i = r0 & 2047;
                const int b1i = (r0 + 8) >> 11, s1i = (r0 + 8) & 2047;
                *(float2*)(Y + (((size_t)(b0i * H_ + h)) * S_ + s0i) * DK_ + dk) = v0;
                *(float2*)(Y + (((size_t)(b1i * H_ + h)) * S_ + s1i) * DK_ + dk) = v1;
            }
        }
    }
}

// ---------------------------------------------------------------------------
// Flash attention (causal), fp32, online softmax — unchanged from R1.
// ---------------------------------------------------------------------------
#define PADW 68
#define SM_TILE (64 * PADW)

__global__ __launch_bounds__(256) void flash_attn(
    const float* __restrict__ Q, const float* __restrict__ K,
    const float* __restrict__ V, float* __restrict__ O)
{
    extern __shared__ float sm[];
    float* Qs = sm;
    float* Ks = sm + SM_TILE;
    float* Vs = sm + 2 * SM_TILE;
    float* Ps = sm + 3 * SM_TILE;

    const int tid = threadIdx.x;
    const int tr  = tid >> 4;
    const int tc  = tid & 15;
    const int qt  = gridDim.x - 1 - blockIdx.x;
    const int bh  = blockIdx.y;

    const float* Qp = Q + ((size_t)bh * S_ + (size_t)qt * 64) * DK_;
    const float* Kp = K + (size_t)bh * S_ * DK_;
    const float* Vp = V + (size_t)bh * S_ * DK_;

    for (int idx = tid; idx < 64 * 64; idx += 256) {
        const int r = idx >> 6, d = idx & 63;
        Qs[d * PADW + r] = Qp[idx] * 0.125f;
    }

    float m_i[4], l_i[4], acc[4][4];
#pragma unroll
    for (int i = 0; i < 4; i++) {
        m_i[i] = -1e30f; l_i[i] = 0.f;
#pragma unroll
        for (int j = 0; j < 4; j++) acc[i][j] = 0.f;
    }

    for (int jt = 0; jt <= qt; jt++) {
        const float* Kt = Kp + (size_t)jt * 64 * DK_;
        const float* Vt = Vp + (size_t)jt * 64 * DK_;

        __syncthreads();
        for (int idx = tid; idx < 64 * 64; idx += 256) {
            const int r = idx >> 6, d = idx & 63;
            Ks[d * PADW + r] = Kt[idx];
            Vs[r * PADW + d] = Vt[idx];
        }
        __syncthreads();

        float s[4][4];
#pragma unroll
        for (int i = 0; i < 4; i++)
#pragma unroll
            for (int j = 0; j < 4; j++) s[i][j] = 0.f;

#pragma unroll 4
        for (int d = 0; d < 64; d++) {
            const float4 a = *(const float4*)&Qs[d * PADW + tr * 4];
            const float4 b = *(const float4*)&Ks[d * PADW + tc * 4];
            s[0][0] = fmaf(a.x, b.x, s[0][0]); s[0][1] = fmaf(a.x, b.y, s[0][1]);
            s[0][2] = fmaf(a.x, b.z, s[0][2]); s[0][3] = fmaf(a.x, b.w, s[0][3]);
            s[1][0] = fmaf(a.y, b.x, s[1][0]); s[1][1] = fmaf(a.y, b.y, s[1][1]);
            s[1][2] = fmaf(a.y, b.z, s[1][2]); s[1][3] = fmaf(a.y, b.w, s[1][3]);
            s[2][0] = fmaf(a.z, b.x, s[2][0]); s[2][1] = fmaf(a.z, b.y, s[2][1]);
            s[2][2] = fmaf(a.z, b.z, s[2][2]); s[2][3] = fmaf(a.z, b.w, s[2][3]);
            s[3][0] = fmaf(a.w, b.x, s[3][0]); s[3][1] = fmaf(a.w, b.y, s[3][1]);
            s[3][2] = fmaf(a.w, b.z, s[3][2]); s[3][3] = fmaf(a.w, b.w, s[3][3]);
        }

        if (jt == qt) {
#pragma unroll
            for (int i = 0; i < 4; i++)
#pragma unroll
                for (int j = 0; j < 4; j++)
                    if (tc * 4 + j > tr * 4 + i) s[i][j] = -1e9f;
        }

#pragma unroll
        for (int i = 0; i < 4; i++) {
            float mt = fmaxf(fmaxf(s[i][0], s[i][1]), fmaxf(s[i][2], s[i][3]));
#pragma unroll
            for (int off = 1; off < 16; off <<= 1)
                mt = fmaxf(mt, __shfl_xor_sync(0xffffffffu, mt, off));
            const float mn = fmaxf(m_i[i], mt);
            const float al = __expf(m_i[i] - mn);
            float rs = 0.f;
#pragma unroll
            for (int j = 0; j < 4; j++) {
                s[i][j] = __expf(s[i][j] - mn);
                rs += s[i][j];
            }
#pragma unroll
            for (int off = 1; off < 16; off <<= 1)
                rs += __shfl_xor_sync(0xffffffffu, rs, off);
            l_i[i] = l_i[i] * al + rs;
            m_i[i] = mn;
#pragma unroll
            for (int j = 0; j < 4; j++) acc[i][j] *= al;
            *(float4*)&Ps[(tr * 4 + i) * PADW + tc * 4] =
                make_float4(s[i][0], s[i][1], s[i][2], s[i][3]);
        }
        __syncthreads();

#pragma unroll 4
        for (int k4 = 0; k4 < 64; k4 += 4) {
            float4 pr[4];
#pragma unroll
            for (int i = 0; i < 4; i++)
                pr[i] = *(const float4*)&Ps[(tr * 4 + i) * PADW + k4];
#pragma unroll
            for (int kk = 0; kk < 4; kk++) {
                const float4 v = *(const float4*)&Vs[(k4 + kk) * PADW + tc * 4];
                const float p0 = (kk == 0) ? pr[0].x : (kk == 1) ? pr[0].y : (kk == 2) ? pr[0].z : pr[0].w;
                const float p1 = (kk == 0) ? pr[1].x : (kk == 1) ? pr[1].y : (kk == 2) ? pr[1].z : pr[1].w;
                const float p2 = (kk == 0) ? pr[2].x : (kk == 1) ? pr[2].y : (kk == 2) ? pr[2].z : pr[2].w;
                const float p3 = (kk == 0) ? pr[3].x : (kk == 1) ? pr[3].y : (kk == 2) ? pr[3].z : pr[3].w;
                acc[0][0] = fmaf(p0, v.x, acc[0][0]); acc[0][1] = fmaf(p0, v.y, acc[0][1]);
                acc[0][2] = fmaf(p0, v.z, acc[0][2]); acc[0][3] = fmaf(p0, v.w, acc[0][3]);
                acc[1][0] = fmaf(p1, v.x, acc[1][0]); acc[1][1] = fmaf(p1, v.y, acc[1][1]);
                acc[1][2] = fmaf(p1, v.z, acc[1][2]); acc[1][3] = fmaf(p1, v.w, acc[1][3]);
                acc[2][0] = fmaf(p2, v.x, acc[2][0]); acc[2][1] = fmaf(p2, v.y, acc[2][1]);
                acc[2][2] = fmaf(p2, v.z, acc[2][2]); acc[2][3] = fmaf(p2, v.w, acc[2][3]);
                acc[3][0] = fmaf(p3, v.x, acc[3][0]); acc[3][1] = fmaf(p3, v.y, acc[3][1]);
                acc[3][2] = fmaf(p3, v.z, acc[3][2]); acc[3][3] = fmaf(p3, v.w, acc[3][3]);
            }
        }
    }

    const int b = bh >> 4, h = bh & 15;
#pragma unroll
    for (int i = 0; i < 4; i++) {
        const float inv = 1.f / l_i[i];
        const int r = qt * 64 + tr * 4 + i;
#pragma unroll
        for (int j = 0; j < 4; j++)
            O[((size_t)(b * S_ + r)) * D_ + h * 64 + tc * 4 + j] = acc[i][j] * inv;
    }
}

// ---------------------------------------------------------------------------
extern "C" void kernel_launch(void* const* d_in, const int* in_sizes, int n_in,
                              void* d_out, int out_size)
{
    const float* x  = (const float*)d_in[0];
    const float* Wq = (const float*)d_in[2];
    const float* bq = (const float*)d_in[3];
    const float* Wk = (const float*)d_in[4];
    const float* bk = (const float*)d_in[5];
    const float* Wv = (const float*)d_in[6];
    const float* bv = (const float*)d_in[7];
    const float* Wo = (const float*)d_in[8];
    const float* bo = (const float*)d_in[9];

    float *qb, *kb, *vb, *cb;
    __nv_bfloat16 *xh, *xl, *wth, *wtl;
    cudaGetSymbolAddress((void**)&qb, g_Q);
    cudaGetSymbolAddress((void**)&kb, g_K);
    cudaGetSymbolAddress((void**)&vb, g_V);
    cudaGetSymbolAddress((void**)&cb, g_ctx);
    cudaGetSymbolAddress((void**)&xh, g_Xhi);
    cudaGetSymbolAddress((void**)&xl, g_Xlo);
    cudaGetSymbolAddress((void**)&wth, g_Wth);
    cudaGetSymbolAddress((void**)&wtl, g_Wtl);

    const int n4 = M_ROWS * D_ / 4;
    const dim3 tg(D_ / 32, D_ / 32);
    const dim3 tb(32, 32);
    const dim3 gg(D_ / 128, M_ROWS / 128);   // (8, 32)

    // split X once
    split_bf16<<<(n4 + 255) / 256, 256>>>(x, xh, xl, n4);

    // Q, K, V projections (HMMA tensor path)
    transpose_split<<<tg, tb>>>(Wq, wth, wtl);
    gemm_tc<<<gg, 256>>>(xh, xl, wth, wtl, bq, qb, 1);
    transpose_split<<<tg, tb>>>(Wk, wth, wtl);
    gemm_tc<<<gg, 256>>>(xh, xl, wth, wtl, bk, kb, 1);
    transpose_split<<<tg, tb>>>(Wv, wth, wtl);
    gemm_tc<<<gg, 256>>>(xh, xl, wth, wtl, bv, vb, 1);

    // attention (fp32)
    const int smem = 4 * SM_TILE * sizeof(float);
    cudaFuncSetAttribute(flash_attn, cudaFuncAttributeMaxDynamicSharedMemorySize, smem);
    const dim3 ga(S_ / 64, BH_);
    flash_attn<<<ga, 256, smem>>>(qb, kb, vb, cb);

    // output projection
    split_bf16<<<(n4 + 255) / 256, 256>>>(cb, xh, xl, n4);
    transpose_split<<<tg, tb>>>(Wo, wth, wtl);
    gemm_tc<<<gg, 256>>>(xh, xl, wth, wtl, bo, (float*)d_out, 0);
}

// round 4
// speedup vs baseline: 2.9154x; 1.6836x over previous
#include <cuda_runtime.h>
#include <cuda_bf16.h>
#include <cstdint>

#define B_   2
#define S_   2048
#define D_   1024
#define H_   16
#define DK_  64
#define BH_  (B_ * H_)
#define M_ROWS (B_ * S_)   // 4096

// Q pre-scale: log2(e) / sqrt(DK)  ->  softmax becomes exp2(s - m)
#define QSCALE 0.18033688011112042f

// ---------------- scratch (static device globals) ----------------
__device__ __nv_bfloat16 g_Xhi[M_ROWS * D_];
__device__ __nv_bfloat16 g_Xlo[M_ROWS * D_];
__device__ __nv_bfloat16 g_Wth[D_ * D_];
__device__ __nv_bfloat16 g_Wtl[D_ * D_];
__device__ __nv_bfloat16 g_Qh[BH_ * S_ * DK_];
__device__ __nv_bfloat16 g_Ql[BH_ * S_ * DK_];
__device__ __nv_bfloat16 g_Kh[BH_ * S_ * DK_];
__device__ __nv_bfloat16 g_Kl[BH_ * S_ * DK_];
__device__ __nv_bfloat16 g_Vh[BH_ * S_ * DK_];
__device__ __nv_bfloat16 g_Vl[BH_ * S_ * DK_];

// ---------------- helpers ----------------
__device__ __forceinline__ uint32_t smem_u32(const void* p) {
    uint32_t a;
    asm("{ .reg .u64 t; cvta.to.shared.u64 t, %1; cvt.u32.u64 %0, t; }" : "=r"(a) : "l"(p));
    return a;
}
__device__ __forceinline__ void ldsm4(uint32_t* r, uint32_t addr) {
    asm volatile("ldmatrix.sync.aligned.m8n8.x4.shared.b16 {%0,%1,%2,%3}, [%4];"
        : "=r"(r[0]), "=r"(r[1]), "=r"(r[2]), "=r"(r[3]) : "r"(addr));
}
__device__ __forceinline__ void ldsm4t(uint32_t* r, uint32_t addr) {
    asm volatile("ldmatrix.sync.aligned.m8n8.x4.trans.shared.b16 {%0,%1,%2,%3}, [%4];"
        : "=r"(r[0]), "=r"(r[1]), "=r"(r[2]), "=r"(r[3]) : "r"(addr));
}
__device__ __forceinline__ void ldsm2(uint32_t* r, uint32_t addr) {
    asm volatile("ldmatrix.sync.aligned.m8n8.x2.shared.b16 {%0,%1}, [%2];"
        : "=r"(r[0]), "=r"(r[1]) : "r"(addr));
}
__device__ __forceinline__ void mma16816(float* c, const uint32_t* a, const uint32_t* b) {
    asm volatile("mma.sync.aligned.m16n8k16.row.col.f32.bf16.bf16.f32 "
        "{%0,%1,%2,%3}, {%4,%5,%6,%7}, {%8,%9}, {%0,%1,%2,%3};"
        : "+f"(c[0]), "+f"(c[1]), "+f"(c[2]), "+f"(c[3])
        : "r"(a[0]), "r"(a[1]), "r"(a[2]), "r"(a[3]), "r"(b[0]), "r"(b[1]));
}
__device__ __forceinline__ void cpa16(uint32_t d, const void* g) {
    asm volatile("cp.async.cg.shared.global [%0], [%1], 16;" :: "r"(d), "l"(g));
}
#define CP_COMMIT() asm volatile("cp.async.commit_group;" ::: "memory")
#define CP_WAIT0()  asm volatile("cp.async.wait_group 0;" ::: "memory")

__device__ __forceinline__ void split2(float a, float b, uint32_t& hi, uint32_t& lo) {
    __nv_bfloat16 ha = __float2bfloat16(a), hb = __float2bfloat16(b);
    __nv_bfloat16 la = __float2bfloat16(a - __bfloat162float(ha));
    __nv_bfloat16 lb = __float2bfloat16(b - __bfloat162float(hb));
    __nv_bfloat162 hp, lp;
    hp.x = ha; hp.y = hb; lp.x = la; lp.y = lb;
    hi = *(uint32_t*)&hp; lo = *(uint32_t*)&lp;
}

// ---------------------------------------------------------------------------
// split fp32 -> bf16 hi/lo pair
// ---------------------------------------------------------------------------
__global__ __launch_bounds__(256) void split_bf16(
    const float* __restrict__ src, __nv_bfloat16* __restrict__ hi,
    __nv_bfloat16* __restrict__ lo, int n4)
{
    int i = blockIdx.x * blockDim.x + threadIdx.x;
    if (i >= n4) return;
    float4 v = ((const float4*)src)[i];
    uint32_t h0, l0, h1, l1;
    split2(v.x, v.y, h0, l0);
    split2(v.z, v.w, h1, l1);
    uint2 hu = {h0, h1}, lu = {l0, l1};
    ((uint2*)hi)[i] = hu;
    ((uint2*)lo)[i] = lu;
}

// ---------------------------------------------------------------------------
// transpose W [K,N] -> Wt [N,K] with bf16 hi/lo split (1024x1024)
// ---------------------------------------------------------------------------
__global__ void transpose_split(const float* __restrict__ W,
                                __nv_bfloat16* __restrict__ hi,
                                __nv_bfloat16* __restrict__ lo)
{
    __shared__ float t[32][33];
    const int k = blockIdx.y * 32 + threadIdx.y;
    const int n = blockIdx.x * 32 + threadIdx.x;
    t[threadIdx.y][threadIdx.x] = W[(size_t)k * D_ + n];
    __syncthreads();
    const int nn = blockIdx.x * 32 + threadIdx.y;
    const int kk = blockIdx.y * 32 + threadIdx.x;
    float v = t[threadIdx.x][threadIdx.y];
    __nv_bfloat16 h = __float2bfloat16(v);
    __nv_bfloat16 l = __float2bfloat16(v - __bfloat162float(h));
    hi[(size_t)nn * D_ + kk] = h;
    lo[(size_t)nn * D_ + kk] = l;
}

// ---------------------------------------------------------------------------
// HMMA GEMM: Y[M,N] = A[M,K] @ Bt[N,K]^T + bias, 3x bf16-split mma.sync.
// mode 0: fp32 row-major out (Yf).  mode 1: bf16 hi/lo scatter to [B,H,S,DK]
// (Yh/Yl), values scaled by `scale`.
// ---------------------------------------------------------------------------
#define ROWB 80
#define TILEB (128 * ROWB)

__global__ __launch_bounds__(256, 1) void gemm_tc(
    const __nv_bfloat16* __restrict__ Ah, const __nv_bfloat16* __restrict__ Al,
    const __nv_bfloat16* __restrict__ Bh, const __nv_bfloat16* __restrict__ Bl,
    const float* __restrict__ bias, float* __restrict__ Yf,
    __nv_bfloat16* __restrict__ Yh, __nv_bfloat16* __restrict__ Yl,
    int mode, float scale)
{
    __shared__ __align__(16) unsigned char smc[4 * TILEB];
    const uint32_t s0  = smem_u32(smc);
    const uint32_t SAh = s0, SAl = s0 + TILEB, SBh = s0 + 2 * TILEB, SBl = s0 + 3 * TILEB;

    const int tid = threadIdx.x, wid = tid >> 5, lane = tid & 31;
    const int wm = wid >> 2, wn = wid & 3;
    const int bm = blockIdx.y * 128, bn = blockIdx.x * 128;

    const int lrow = tid >> 1;
    const int lcol = (tid & 1) * 16;
    const __nv_bfloat16* gAh = Ah + (size_t)(bm + lrow) * 1024 + lcol;
    const __nv_bfloat16* gAl = Al + (size_t)(bm + lrow) * 1024 + lcol;
    const __nv_bfloat16* gBh = Bh + (size_t)(bn + lrow) * 1024 + lcol;
    const __nv_bfloat16* gBl = Bl + (size_t)(bn + lrow) * 1024 + lcol;
    const uint32_t sts = (uint32_t)lrow * ROWB + (uint32_t)(tid & 1) * 32;

    const uint32_t a_off = (uint32_t)(lane & 15) * ROWB + (uint32_t)(lane >> 4) * 16;
    const uint32_t b_off = (uint32_t)(lane & 7) * ROWB + (uint32_t)((lane >> 3) & 1) * 16;
    const uint32_t aBase = (uint32_t)(wm * 64) * ROWB + a_off;
    const uint32_t bBase = (uint32_t)(wn * 32) * ROWB + b_off;

    float acc[16][4];
#pragma unroll
    for (int i = 0; i < 16; i++)
#pragma unroll
        for (int j = 0; j < 4; j++) acc[i][j] = 0.f;

    uint4 pre[8];
#pragma unroll
    for (int t = 0; t < 2; t++) {
        pre[0 + t] = *(const uint4*)(gAh + t * 8);
        pre[2 + t] = *(const uint4*)(gAl + t * 8);
        pre[4 + t] = *(const uint4*)(gBh + t * 8);
        pre[6 + t] = *(const uint4*)(gBl + t * 8);
    }

    for (int ks = 0; ks < 32; ks++) {
        *(uint4*)(smc + 0 * TILEB + sts)      = pre[0];
        *(uint4*)(smc + 0 * TILEB + sts + 16) = pre[1];
        *(uint4*)(smc + 1 * TILEB + sts)      = pre[2];
        *(uint4*)(smc + 1 * TILEB + sts + 16) = pre[3];
        *(uint4*)(smc + 2 * TILEB + sts)      = pre[4];
        *(uint4*)(smc + 2 * TILEB + sts + 16) = pre[5];
        *(uint4*)(smc + 3 * TILEB + sts)      = pre[6];
        *(uint4*)(smc + 3 * TILEB + sts + 16) = pre[7];
        __syncthreads();

        if (ks < 31) {
            const int ko = (ks + 1) * 32;
#pragma unroll
            for (int t = 0; t < 2; t++) {
                pre[0 + t] = *(const uint4*)(gAh + ko + t * 8);
                pre[2 + t] = *(const uint4*)(gAl + ko + t * 8);
                pre[4 + t] = *(const uint4*)(gBh + ko + t * 8);
                pre[6 + t] = *(const uint4*)(gBl + ko + t * 8);
            }
        }

#pragma unroll
        for (int h = 0; h < 2; h++) {
            uint32_t fAh[4][4], fAl[4][4], fB[4][2];
#pragma unroll
            for (int mt = 0; mt < 4; mt++) {
                const uint32_t ra = aBase + (uint32_t)(mt * 16) * ROWB + (uint32_t)h * 32;
                ldsm4(fAh[mt], SAh + ra);
                ldsm4(fAl[mt], SAl + ra);
            }
#pragma unroll
            for (int nt = 0; nt < 4; nt++)
                ldsm2(fB[nt], SBh + bBase + (uint32_t)(nt * 8) * ROWB + (uint32_t)h * 32);
#pragma unroll
            for (int mt = 0; mt < 4; mt++)
#pragma unroll
                for (int nt = 0; nt < 4; nt++) {
                    mma16816(acc[mt * 4 + nt], fAh[mt], fB[nt]);
                    mma16816(acc[mt * 4 + nt], fAl[mt], fB[nt]);
                }
#pragma unroll
            for (int nt = 0; nt < 4; nt++)
                ldsm2(fB[nt], SBl + bBase + (uint32_t)(nt * 8) * ROWB + (uint32_t)h * 32);
#pragma unroll
            for (int mt = 0; mt < 4; mt++)
#pragma unroll
                for (int nt = 0; nt < 4; nt++)
                    mma16816(acc[mt * 4 + nt], fAh[mt], fB[nt]);
        }
        __syncthreads();
    }

    const int qr = lane >> 2, qc = (lane & 3) * 2;
#pragma unroll
    for (int mt = 0; mt < 4; mt++) {
#pragma unroll
        for (int nt = 0; nt < 4; nt++) {
            const float* a4 = acc[mt * 4 + nt];
            const int r0 = bm + wm * 64 + mt * 16 + qr;
            const int cn = bn + wn * 32 + nt * 8 + qc;
            const float b0 = bias[cn], b1 = bias[cn + 1];
            if (mode == 0) {
                float2 v0 = {a4[0] + b0, a4[1] + b1};
                float2 v1 = {a4[2] + b0, a4[3] + b1};
                *(float2*)(Yf + (size_t)r0 * 1024 + cn) = v0;
                *(float2*)(Yf + (size_t)(r0 + 8) * 1024 + cn) = v1;
            } else {
                const float w0 = (a4[0] + b0) * scale, w1 = (a4[1] + b1) * scale;
                const float w2 = (a4[2] + b0) * scale, w3 = (a4[3] + b1) * scale;
                const int h  = cn >> 6, dk = cn & 63;
                const int b0i = r0 >> 11, s0i = r0 & 2047;
                const int b1i = (r0 + 8) >> 11, s1i = (r0 + 8) & 2047;
                const size_t o0 = (((size_t)(b0i * H_ + h)) * S_ + s0i) * DK_ + dk;
                const size_t o1 = (((size_t)(b1i * H_ + h)) * S_ + s1i) * DK_ + dk;
                uint32_t h0, l0, h1, l1;
                split2(w0, w1, h0, l0);
                split2(w2, w3, h1, l1);
                *(uint32_t*)(Yh + o0) = h0; *(uint32_t*)(Yl + o0) = l0;
                *(uint32_t*)(Yh + o1) = h1; *(uint32_t*)(Yl + o1) = l1;
            }
        }
    }
}

// ---------------------------------------------------------------------------
// Tensor-core flash attention (causal). 128 q-rows/CTA, 8 warps (16 rows each),
// 64-key tiles, cp.async double buffer, 3-term bf16-split HMMA for both GEMMs.
// Q was pre-scaled by log2(e)/8 at projection -> p = exp2(s - m).
// Writes ctx as bf16 hi/lo into the out-projection input buffers.
// smem: buf[i] (i=0,1) at i*32768: Kh +0, Kl +8192, Vh +16384, Vl +24576.
// Q staged once in buf0 (Qh +0, Ql +16384) before the loop.
// ---------------------------------------------------------------------------
__global__ __launch_bounds__(256, 1) void flash_attn_tc(
    const __nv_bfloat16* __restrict__ Qh, const __nv_bfloat16* __restrict__ Ql,
    const __nv_bfloat16* __restrict__ Kh, const __nv_bfloat16* __restrict__ Kl,
    const __nv_bfloat16* __restrict__ Vh, const __nv_bfloat16* __restrict__ Vl,
    __nv_bfloat16* __restrict__ Ohi, __nv_bfloat16* __restrict__ Olo)
{
    extern __shared__ __align__(16) unsigned char sm[];
    const uint32_t s0 = smem_u32(sm);

    const int tid = threadIdx.x, wid = tid >> 5, lane = tid & 31;
    const int qt = 15 - blockIdx.x;          // heavy tiles first
    const int bh = blockIdx.y;
    const int qbase = qt * 128;
    const int njt = 2 * (qt + 1);
    const int rb = wid * 16;                 // warp's q-row base (local)

    // ---- stage Q (hi at s0, lo at s0+16384), 128 rows x 128B, swizzled ----
    {
        const int arr = tid >> 7;            // 0=hi 1=lo
        const int t2 = tid & 127;
        const int rsub = t2 >> 3;            // row within pass group
        const int ch = t2 & 7;
        const __nv_bfloat16* base = (arr ? Ql : Qh) + ((size_t)bh * S_ + qbase) * DK_;
        const uint32_t db = s0 + (uint32_t)arr * 16384;
#pragma unroll
        for (int p = 0; p < 8; p++) {
            const int row = p * 16 + rsub;
            *(uint4*)(sm + (db - s0) + (uint32_t)row * 128 + (uint32_t)((ch ^ (row & 7)) << 4)) =
                *(const uint4*)(base + (size_t)row * 64 + ch * 8);
        }
    }
    __syncthreads();

    // ---- load Q fragments ----
    uint32_t qfh[4][4], qfl[4][4];
    {
        const int row = rb + (lane & 15);
        const int r7 = row & 7;
#pragma unroll
        for (int kk = 0; kk < 4; kk++) {
            const uint32_t a = s0 + (uint32_t)row * 128 +
                (uint32_t)(((2 * kk + (lane >> 4)) ^ r7) << 4);
            ldsm4(qfh[kk], a);
            ldsm4(qfl[kk], a + 16384);
        }
    }
    __syncthreads();

    // ---- KV copy geometry (per thread, fixed) ----
    const int a4  = tid >> 6;                // 0..3: Kh,Kl,Vh,Vl
    const int t4  = tid & 63;
    const int rs4 = t4 >> 3;                 // row sub
    const int ch4 = t4 & 7;                  // chunk
    const __nv_bfloat16* kvsrc =
        (a4 == 0) ? Kh : (a4 == 1) ? Kl : (a4 == 2) ? Vh : Vl;
    kvsrc += (size_t)bh * S_ * DK_;
    const uint32_t kvdst = s0 + (uint32_t)a4 * 8192;

    // stage key-tile 0 into buf 0
    {
        const __nv_bfloat16* g = kvsrc;
#pragma unroll
        for (int p = 0; p < 8; p++) {
            const int row = p * 8 + rs4;
            cpa16(kvdst + (uint32_t)row * 128 + (uint32_t)((ch4 ^ (row & 7)) << 4),
                  g + (size_t)row * 64 + ch4 * 8);
        }
    }
    CP_COMMIT();

    float m_i[2] = {-1e30f, -1e30f};
    float l_i[2] = {0.f, 0.f};
    float oac[8][4];
#pragma unroll
    for (int t = 0; t < 8; t++)
#pragma unroll
        for (int e = 0; e < 4; e++) oac[t][e] = 0.f;

    for (int jt = 0; jt < njt; jt++) {
        CP_WAIT0();
        __syncthreads();
        const uint32_t bb = s0 + (uint32_t)(jt & 1) * 32768;

        if (jt + 1 < njt) {
            const __nv_bfloat16* g = kvsrc + (size_t)(jt + 1) * 64 * 64;
            const uint32_t db = kvdst + (uint32_t)((jt + 1) & 1) * 32768;
#pragma unroll
            for (int p = 0; p < 8; p++) {
                const int row = p * 8 + rs4;
                cpa16(db + (uint32_t)row * 128 + (uint32_t)((ch4 ^ (row & 7)) << 4),
                      g + (size_t)row * 64 + ch4 * 8);
            }
            CP_COMMIT();
        }

        // ---- scores: S = Q' @ K^T (3-term split) ----
        float sc[8][4];
#pragma unroll
        for (int t = 0; t < 8; t++)
#pragma unroll
            for (int e = 0; e < 4; e++) sc[t][e] = 0.f;

#pragma unroll
        for (int kk = 0; kk < 4; kk++) {
#pragma unroll
            for (int j = 0; j < 4; j++) {
                const int krow = 16 * j + (lane & 7) + ((lane & 16) >> 1);
                const uint32_t ka = bb + (uint32_t)krow * 128 +
                    (uint32_t)(((2 * kk + ((lane >> 3) & 1)) ^ (krow & 7)) << 4);
                uint32_t bhf[4], blf[4];
                ldsm4(bhf, ka);          // K hi
                ldsm4(blf, ka + 8192);   // K lo
                mma16816(sc[2 * j],     qfh[kk], bhf + 0);
                mma16816(sc[2 * j + 1], qfh[kk], bhf + 2);
                mma16816(sc[2 * j],     qfh[kk], blf + 0);
                mma16816(sc[2 * j + 1], qfh[kk], blf + 2);
                mma16816(sc[2 * j],     qfl[kk], bhf + 0);
                mma16816(sc[2 * j + 1], qfl[kk], bhf + 2);
            }
        }

        // ---- causal mask (only the diagonal pair of tiles) ----
        if (jt >= njt - 2) {
            const int kb = jt * 64;
#pragma unroll
            for (int t = 0; t < 8; t++)
#pragma unroll
                for (int e = 0; e < 4; e++) {
                    const int kg = kb + t * 8 + 2 * (lane & 3) + (e & 1);
                    const int qg = qbase + rb + (lane >> 2) + (e >> 1) * 8;
                    if (kg > qg) sc[t][e] = -1e9f;
                }
        }

        // ---- online softmax (rows r and r+8) ----
#pragma unroll
        for (int h = 0; h < 2; h++) {
            float mr = -1e30f;
#pragma unroll
            for (int t = 0; t < 8; t++)
                mr = fmaxf(mr, fmaxf(sc[t][2 * h], sc[t][2 * h + 1]));
            mr = fmaxf(mr, __shfl_xor_sync(0xffffffffu, mr, 1));
            mr = fmaxf(mr, __shfl_xor_sync(0xffffffffu, mr, 2));
            const float mn = fmaxf(m_i[h], mr);
            const float alpha = exp2f(m_i[h] - mn);
            m_i[h] = mn;
            float rs = 0.f;
#pragma unroll
            for (int t = 0; t < 8; t++) {
                sc[t][2 * h]     = exp2f(sc[t][2 * h] - mn);
                sc[t][2 * h + 1] = exp2f(sc[t][2 * h + 1] - mn);
                rs += sc[t][2 * h] + sc[t][2 * h + 1];
            }
            rs += __shfl_xor_sync(0xffffffffu, rs, 1);
            rs += __shfl_xor_sync(0xffffffffu, rs, 2);
            l_i[h] = l_i[h] * alpha + rs;
#pragma unroll
            for (int t = 0; t < 8; t++) {
                oac[t][2 * h]     *= alpha;
                oac[t][2 * h + 1] *= alpha;
            }
        }

        // ---- PV: acc += P @ V (3-term split, V via ldmatrix.trans) ----
#pragma unroll
        for (int kk = 0; kk < 4; kk++) {
            uint32_t pah[4], pal[4];
            split2(sc[2 * kk][0],     sc[2 * kk][1],     pah[0], pal[0]);
            split2(sc[2 * kk][2],     sc[2 * kk][3],     pah[1], pal[1]);
            split2(sc[2 * kk + 1][0], sc[2 * kk + 1][1], pah[2], pal[2]);
            split2(sc[2 * kk + 1][2], sc[2 * kk + 1][3], pah[3], pal[3]);

            const int vrow = 16 * kk + (lane & 15);
            const int vr7 = vrow & 7;
#pragma unroll
            for (int j = 0; j < 4; j++) {
                const uint32_t va = bb + 16384 + (uint32_t)vrow * 128 +
                    (uint32_t)(((2 * j + (lane >> 4)) ^ vr7) << 4);
                uint32_t vhf[4], vlf[4];
                ldsm4t(vhf, va);          // V hi
                ldsm4t(vlf, va + 8192);   // V lo
                mma16816(oac[2 * j],     pah, vhf + 0);
                mma16816(oac[2 * j + 1], pah, vhf + 2);
                mma16816(oac[2 * j],     pah, vlf + 0);
                mma16816(oac[2 * j + 1], pah, vlf + 2);
                mma16816(oac[2 * j],     pal, vhf + 0);
                mma16816(oac[2 * j + 1], pal, vhf + 2);
            }
        }
    }

    // ---- epilogue: ctx hi/lo -> [M_ROWS, D] at (b*2048+q, h*64+dk) ----
    const int bb_ = bh >> 4, hh = bh & 15;
#pragma unroll
    for (int h = 0; h < 2; h++) {
        const float invl = 1.f / l_i[h];
        const int rg = qbase + rb + (lane >> 2) + 8 * h;
        const size_t mrow = (size_t)(bb_ * 2048 + rg) * 1024;
#pragma unroll
        for (int t = 0; t < 8; t++) {
            const float v0 = oac[t][2 * h] * invl;
            const float v1 = oac[t][2 * h + 1] * invl;
            const int col = hh * 64 + t * 8 + 2 * (lane & 3);
            uint32_t hi, lo;
            split2(v0, v1, hi, lo);
            *(uint32_t*)(Ohi + mrow + col) = hi;
            *(uint32_t*)(Olo + mrow + col) = lo;
        }
    }
}

// ---------------------------------------------------------------------------
extern "C" void kernel_launch(void* const* d_in, const int* in_sizes, int n_in,
                              void* d_out, int out_size)
{
    const float* x  = (const float*)d_in[0];
    const float* Wq = (const float*)d_in[2];
    const float* bq = (const float*)d_in[3];
    const float* Wk = (const float*)d_in[4];
    const float* bk = (const float*)d_in[5];
    const float* Wv = (const float*)d_in[6];
    const float* bv = (const float*)d_in[7];
    const float* Wo = (const float*)d_in[8];
    const float* bo = (const float*)d_in[9];

    __nv_bfloat16 *xh, *xl, *wth, *wtl, *qh, *ql, *kh, *kl, *vh, *vl;
    cudaGetSymbolAddress((void**)&xh, g_Xhi);
    cudaGetSymbolAddress((void**)&xl, g_Xlo);
    cudaGetSymbolAddress((void**)&wth, g_Wth);
    cudaGetSymbolAddress((void**)&wtl, g_Wtl);
    cudaGetSymbolAddress((void**)&qh, g_Qh);
    cudaGetSymbolAddress((void**)&ql, g_Ql);
    cudaGetSymbolAddress((void**)&kh, g_Kh);
    cudaGetSymbolAddress((void**)&kl, g_Kl);
    cudaGetSymbolAddress((void**)&vh, g_Vh);
    cudaGetSymbolAddress((void**)&vl, g_Vl);

    const int n4 = M_ROWS * D_ / 4;
    const dim3 tg(D_ / 32, D_ / 32);
    const dim3 tb(32, 32);
    const dim3 gg(D_ / 128, M_ROWS / 128);   // (8, 32)

    split_bf16<<<(n4 + 255) / 256, 256>>>(x, xh, xl, n4);

    transpose_split<<<tg, tb>>>(Wq, wth, wtl);
    gemm_tc<<<gg, 256>>>(xh, xl, wth, wtl, bq, nullptr, qh, ql, 1, QSCALE);
    transpose_split<<<tg, tb>>>(Wk, wth, wtl);
    gemm_tc<<<gg, 256>>>(xh, xl, wth, wtl, bk, nullptr, kh, kl, 1, 1.0f);
    transpose_split<<<tg, tb>>>(Wv, wth, wtl);
    gemm_tc<<<gg, 256>>>(xh, xl, wth, wtl, bv, nullptr, vh, vl, 1, 1.0f);

    // tensor-core attention; writes ctx hi/lo into xh/xl
    const int asmem = 65536;
    cudaFuncSetAttribute(flash_attn_tc, cudaFuncAttributeMaxDynamicSharedMemorySize, asmem);
    const dim3 ga(S_ / 128, BH_);            // (16, 32)
    flash_attn_tc<<<ga, 256, asmem>>>(qh, ql, kh, kl, vh, vl, xh, xl);

    transpose_split<<<tg, tb>>>(Wo, wth, wtl);
    gemm_tc<<<gg, 256>>>(xh, xl, wth, wtl, bo, (float*)d_out, nullptr, nullptr, 0, 1.0f);
}

// round 5
// speedup vs baseline: 3.2187x; 1.1040x over previous
#include <cuda_runtime.h>
#include <cuda_bf16.h>
#include <cstdint>

#define B_   2
#define S_   2048
#define D_   1024
#define H_   16
#define DK_  64
#define BH_  (B_ * H_)
#define M_ROWS (B_ * S_)   // 4096

// Q pre-scale: log2(e) / sqrt(DK)  ->  softmax becomes exp2(s - m)
#define QSCALE 0.18033688011112042f

// ---------------- scratch (static device globals) ----------------
__device__ __nv_bfloat16 g_Xhi[M_ROWS * D_];
__device__ __nv_bfloat16 g_Xlo[M_ROWS * D_];
__device__ __nv_bfloat16 g_Wth[3 * D_ * D_];
__device__ __nv_bfloat16 g_Wtl[3 * D_ * D_];
__device__ __nv_bfloat16 g_Qh[BH_ * S_ * DK_];
__device__ __nv_bfloat16 g_Ql[BH_ * S_ * DK_];
__device__ __nv_bfloat16 g_Kh[BH_ * S_ * DK_];
__device__ __nv_bfloat16 g_Kl[BH_ * S_ * DK_];
__device__ __nv_bfloat16 g_Vh[BH_ * S_ * DK_];
__device__ __nv_bfloat16 g_Vl[BH_ * S_ * DK_];

// ---------------- helpers ----------------
__device__ __forceinline__ uint32_t smem_u32(const void* p) {
    uint32_t a;
    asm("{ .reg .u64 t; cvta.to.shared.u64 t, %1; cvt.u32.u64 %0, t; }" : "=r"(a) : "l"(p));
    return a;
}
__device__ __forceinline__ void ldsm4(uint32_t* r, uint32_t addr) {
    asm volatile("ldmatrix.sync.aligned.m8n8.x4.shared.b16 {%0,%1,%2,%3}, [%4];"
        : "=r"(r[0]), "=r"(r[1]), "=r"(r[2]), "=r"(r[3]) : "r"(addr));
}
__device__ __forceinline__ void ldsm4t(uint32_t* r, uint32_t addr) {
    asm volatile("ldmatrix.sync.aligned.m8n8.x4.trans.shared.b16 {%0,%1,%2,%3}, [%4];"
        : "=r"(r[0]), "=r"(r[1]), "=r"(r[2]), "=r"(r[3]) : "r"(addr));
}
__device__ __forceinline__ void mma16816(float* c, const uint32_t* a, const uint32_t* b) {
    asm volatile("mma.sync.aligned.m16n8k16.row.col.f32.bf16.bf16.f32 "
        "{%0,%1,%2,%3}, {%4,%5,%6,%7}, {%8,%9}, {%0,%1,%2,%3};"
        : "+f"(c[0]), "+f"(c[1]), "+f"(c[2]), "+f"(c[3])
        : "r"(a[0]), "r"(a[1]), "r"(a[2]), "r"(a[3]), "r"(b[0]), "r"(b[1]));
}
__device__ __forceinline__ void cpa16(uint32_t d, const void* g) {
    asm volatile("cp.async.cg.shared.global [%0], [%1], 16;" :: "r"(d), "l"(g));
}
#define CP_COMMIT() asm volatile("cp.async.commit_group;" ::: "memory")
#define CP_WAIT0()  asm volatile("cp.async.wait_group 0;" ::: "memory")
#define CP_WAIT1()  asm volatile("cp.async.wait_group 1;" ::: "memory")

__device__ __forceinline__ void split2(float a, float b, uint32_t& hi, uint32_t& lo) {
    __nv_bfloat16 ha = __float2bfloat16(a), hb = __float2bfloat16(b);
    __nv_bfloat16 la = __float2bfloat16(a - __bfloat162float(ha));
    __nv_bfloat16 lb = __float2bfloat16(b - __bfloat162float(hb));
    __nv_bfloat162 hp, lp;
    hp.x = ha; hp.y = hb; lp.x = la; lp.y = lb;
    hi = *(uint32_t*)&hp; lo = *(uint32_t*)&lp;
}

// ---------------------------------------------------------------------------
// split fp32 -> bf16 hi/lo pair
// ---------------------------------------------------------------------------
__global__ __launch_bounds__(256) void split_bf16(
    const float* __restrict__ src, __nv_bfloat16* __restrict__ hi,
    __nv_bfloat16* __restrict__ lo, int n4)
{
    int i = blockIdx.x * blockDim.x + threadIdx.x;
    if (i >= n4) return;
    float4 v = ((const float4*)src)[i];
    uint32_t h0, l0, h1, l1;
    split2(v.x, v.y, h0, l0);
    split2(v.z, v.w, h1, l1);
    uint2 hu = {h0, h1}, lu = {l0, l1};
    ((uint2*)hi)[i] = hu;
    ((uint2*)lo)[i] = lu;
}

// ---------------------------------------------------------------------------
// transpose W [K,N] -> Wt [z*1024 + N, K] with bf16 hi/lo split.
// grid.z selects source (W0/W1/W2). For single-W use grid.z=1.
// ---------------------------------------------------------------------------
__global__ void transpose_split(const float* __restrict__ W0,
                                const float* __restrict__ W1,
                                const float* __restrict__ W2,
                                __nv_bfloat16* __restrict__ hi,
                                __nv_bfloat16* __restrict__ lo)
{
    __shared__ float t[32][33];
    const float* W = (blockIdx.z == 0) ? W0 : (blockIdx.z == 1) ? W1 : W2;
    const int k = blockIdx.y * 32 + threadIdx.y;
    const int n = blockIdx.x * 32 + threadIdx.x;
    t[threadIdx.y][threadIdx.x] = W[(size_t)k * D_ + n];
    __syncthreads();
    const int nn = blockIdx.x * 32 + threadIdx.y + blockIdx.z * D_;
    const int kk = blockIdx.y * 32 + threadIdx.x;
    float v = t[threadIdx.x][threadIdx.y];
    __nv_bfloat16 h = __float2bfloat16(v);
    __nv_bfloat16 l = __float2bfloat16(v - __bfloat162float(h));
    hi[(size_t)nn * D_ + kk] = h;
    lo[(size_t)nn * D_ + kk] = l;
}

// ---------------------------------------------------------------------------
// HMMA GEMM with cp.async 3-stage pipeline, 3x bf16-split mma.sync.
// A[M=4096, K=1024] @ Bt[N, K=1024]^T + bias.
// mode 0: fp32 row-major out (grid.x=8, bias=b0, out=Yf).
// mode 1: fused QKV (grid.x=24): proj = bn>>10 selects bias b0/b1/b2 and
//         output pair (Qh/Ql, Kh/Kl, Vh/Vl); Q scaled by QSCALE. Scatter to
//         [B,H,S,DK] bf16 hi/lo.
// smem: 3 stages x 40960B; stage: Ah +0, Al +10240, Bh +20480, Bl +30720,
//       each 128 rows x 80B (64B data + 16B pad).
// ---------------------------------------------------------------------------
#define GROWB 80
#define SLABB (128 * GROWB)       // 10240
#define STAGEB (4 * SLABB)        // 40960
#define GSMEM (3 * STAGEB)        // 122880

__global__ __launch_bounds__(256) void gemm_tc(
    const __nv_bfloat16* __restrict__ Ah, const __nv_bfloat16* __restrict__ Al,
    const __nv_bfloat16* __restrict__ Bh, const __nv_bfloat16* __restrict__ Bl,
    const float* __restrict__ b0, const float* __restrict__ b1,
    const float* __restrict__ b2, float* __restrict__ Yf,
    __nv_bfloat16* __restrict__ Qh, __nv_bfloat16* __restrict__ Ql,
    __nv_bfloat16* __restrict__ Kh, __nv_bfloat16* __restrict__ Kl,
    __nv_bfloat16* __restrict__ Vh, __nv_bfloat16* __restrict__ Vl,
    int mode)
{
    extern __shared__ __align__(16) unsigned char dsm[];
    const uint32_t s0 = smem_u32(dsm);

    const int tid = threadIdx.x, wid = tid >> 5, lane = tid & 31;
    const int wm = wid >> 2, wn = wid & 3;
    const int bm = blockIdx.y * 128, bn = blockIdx.x * 128;

    // ---- cp.async geometry: 64 threads per array slab ----
    const int a4 = tid >> 6, t4 = tid & 63;
    const __nv_bfloat16* gsrc =
        (a4 == 0) ? Ah : (a4 == 1) ? Al : (a4 == 2) ? Bh : Bl;
    gsrc += (size_t)((a4 < 2) ? bm : bn) * 1024;
    const uint32_t slab = s0 + (uint32_t)a4 * SLABB;

    // ---- ldmatrix addressing ----
    const uint32_t aRow = (uint32_t)(wm * 64 + (lane & 15));
    const uint32_t aCol = (uint32_t)(lane >> 4) * 16;
    // B via ldsm4: m = lane>>3; row = wn*32 + g*16 + (m>>1)*8 + (lane&7); koff = (m&1)*16
    const uint32_t bRow0 = (uint32_t)(wn * 32 + ((lane >> 4) & 1) * 8 + (lane & 7));
    const uint32_t bKoff = (uint32_t)((lane >> 3) & 1) * 16;

    float acc[16][4];
#pragma unroll
    for (int i = 0; i < 16; i++)
#pragma unroll
        for (int j = 0; j < 4; j++) acc[i][j] = 0.f;

    // issue one stage of cp.async (8 x 16B per thread)
    auto issue = [&](int ks) {
        const uint32_t st = slab + (uint32_t)(ks % 3) * STAGEB;
        const __nv_bfloat16* g = gsrc + ks * 32;
#pragma unroll
        for (int p = 0; p < 8; p++) {
            const int idx = p * 64 + t4;
            const int row = idx >> 2, ch = idx & 3;
            cpa16(st + (uint32_t)row * GROWB + (uint32_t)ch * 16,
                  g + (size_t)row * 1024 + ch * 8);
        }
        CP_COMMIT();
    };

    issue(0);
    issue(1);

    for (int ks = 0; ks < 32; ks++) {
        if (ks == 31) { CP_WAIT0(); } else { CP_WAIT1(); }
        __syncthreads();
        if (ks + 2 < 32) issue(ks + 2);

        const uint32_t sb  = s0 + (uint32_t)(ks % 3) * STAGEB;
        const uint32_t SAh = sb, SAl = sb + SLABB;
        const uint32_t SBh = sb + 2 * SLABB, SBl = sb + 3 * SLABB;

#pragma unroll
        for (int h = 0; h < 2; h++) {
            uint32_t fAh[4][4], fAl[4][4], fB[4][2];
#pragma unroll
            for (int mt = 0; mt < 4; mt++) {
                const uint32_t ra = (aRow + (uint32_t)(mt * 16)) * GROWB +
                                    (uint32_t)h * 32 + aCol;
                ldsm4(fAh[mt], SAh + ra);
                ldsm4(fAl[mt], SAl + ra);
            }
            // B hi: 2x ldsm4 cover nt 0..3
#pragma unroll
            for (int g = 0; g < 2; g++) {
                uint32_t r[4];
                ldsm4(r, SBh + (bRow0 + (uint32_t)(g * 16)) * GROWB +
                         (uint32_t)h * 32 + bKoff);
                fB[g * 2][0] = r[0]; fB[g * 2][1] = r[1];
                fB[g * 2 + 1][0] = r[2]; fB[g * 2 + 1][1] = r[3];
            }
#pragma unroll
            for (int mt = 0; mt < 4; mt++)
#pragma unroll
                for (int nt = 0; nt < 4; nt++) {
                    mma16816(acc[mt * 4 + nt], fAh[mt], fB[nt]);
                    mma16816(acc[mt * 4 + nt], fAl[mt], fB[nt]);
                }
            // B lo
#pragma unroll
            for (int g = 0; g < 2; g++) {
                uint32_t r[4];
                ldsm4(r, SBl + (bRow0 + (uint32_t)(g * 16)) * GROWB +
                         (uint32_t)h * 32 + bKoff);
                fB[g * 2][0] = r[0]; fB[g * 2][1] = r[1];
                fB[g * 2 + 1][0] = r[2]; fB[g * 2 + 1][1] = r[3];
            }
#pragma unroll
            for (int mt = 0; mt < 4; mt++)
#pragma unroll
                for (int nt = 0; nt < 4; nt++)
                    mma16816(acc[mt * 4 + nt], fAh[mt], fB[nt]);
        }
        __syncthreads();
    }

    // ---- epilogue ----
    const int qr = lane >> 2, qc = (lane & 3) * 2;
    const int proj = bn >> 10;                   // 0..2 in mode 1
    const float* bias = (proj == 0) ? b0 : (proj == 1) ? b1 : b2;
    const float scale = (mode == 1 && proj == 0) ? QSCALE : 1.0f;
    __nv_bfloat16* Yh = (proj == 0) ? Qh : (proj == 1) ? Kh : Vh;
    __nv_bfloat16* Yl = (proj == 0) ? Ql : (proj == 1) ? Kl : Vl;
    const int bnl = bn & 1023;

#pragma unroll
    for (int mt = 0; mt < 4; mt++) {
#pragma unroll
        for (int nt = 0; nt < 4; nt++) {
            const float* a4p = acc[mt * 4 + nt];
            const int r0 = bm + wm * 64 + mt * 16 + qr;
            const int cn = bnl + wn * 32 + nt * 8 + qc;
            const float bv0 = bias[cn], bv1 = bias[cn + 1];
            if (mode == 0) {
                float2 v0 = {a4p[0] + bv0, a4p[1] + bv1};
                float2 v1 = {a4p[2] + bv0, a4p[3] + bv1};
                *(float2*)(Yf + (size_t)r0 * 1024 + cn) = v0;
                *(float2*)(Yf + (size_t)(r0 + 8) * 1024 + cn) = v1;
            } else {
                const float w0 = (a4p[0] + bv0) * scale, w1 = (a4p[1] + bv1) * scale;
                const float w2 = (a4p[2] + bv0) * scale, w3 = (a4p[3] + bv1) * scale;
                const int h  = cn >> 6, dk = cn & 63;
                const int b0i = r0 >> 11, s0i = r0 & 2047;
                const int b1i = (r0 + 8) >> 11, s1i = (r0 + 8) & 2047;
                const size_t o0 = (((size_t)(b0i * H_ + h)) * S_ + s0i) * DK_ + dk;
                const size_t o1 = (((size_t)(b1i * H_ + h)) * S_ + s1i) * DK_ + dk;
                uint32_t h0, l0, h1, l1;
                split2(w0, w1, h0, l0);
                split2(w2, w3, h1, l1);
                *(uint32_t*)(Yh + o0) = h0; *(uint32_t*)(Yl + o0) = l0;
                *(uint32_t*)(Yh + o1) = h1; *(uint32_t*)(Yl + o1) = l1;
            }
        }
    }
}

// ---------------------------------------------------------------------------
// Tensor-core flash attention (causal) — unchanged from R4.
// ---------------------------------------------------------------------------
__global__ __launch_bounds__(256, 1) void flash_attn_tc(
    const __nv_bfloat16* __restrict__ Qh, const __nv_bfloat16* __restrict__ Ql,
    const __nv_bfloat16* __restrict__ Kh, const __nv_bfloat16* __restrict__ Kl,
    const __nv_bfloat16* __restrict__ Vh, const __nv_bfloat16* __restrict__ Vl,
    __nv_bfloat16* __restrict__ Ohi, __nv_bfloat16* __restrict__ Olo)
{
    extern __shared__ __align__(16) unsigned char sm[];
    const uint32_t s0 = smem_u32(sm);

    const int tid = threadIdx.x, wid = tid >> 5, lane = tid & 31;
    const int qt = 15 - blockIdx.x;
    const int bh = blockIdx.y;
    const int qbase = qt * 128;
    const int njt = 2 * (qt + 1);
    const int rb = wid * 16;

    {
        const int arr = tid >> 7;
        const int t2 = tid & 127;
        const int rsub = t2 >> 3;
        const int ch = t2 & 7;
        const __nv_bfloat16* base = (arr ? Ql : Qh) + ((size_t)bh * S_ + qbase) * DK_;
        const uint32_t db = (uint32_t)arr * 16384;
#pragma unroll
        for (int p = 0; p < 8; p++) {
            const int row = p * 16 + rsub;
            *(uint4*)(sm + db + (uint32_t)row * 128 + (uint32_t)((ch ^ (row & 7)) << 4)) =
                *(const uint4*)(base + (size_t)row * 64 + ch * 8);
        }
    }
    __syncthreads();

    uint32_t qfh[4][4], qfl[4][4];
    {
        const int row = rb + (lane & 15);
        const int r7 = row & 7;
#pragma unroll
        for (int kk = 0; kk < 4; kk++) {
            const uint32_t a = s0 + (uint32_t)row * 128 +
                (uint32_t)(((2 * kk + (lane >> 4)) ^ r7) << 4);
            ldsm4(qfh[kk], a);
            ldsm4(qfl[kk], a + 16384);
        }
    }
    __syncthreads();

    const int a4  = tid >> 6;
    const int t4  = tid & 63;
    const int rs4 = t4 >> 3;
    const int ch4 = t4 & 7;
    const __nv_bfloat16* kvsrc =
        (a4 == 0) ? Kh : (a4 == 1) ? Kl : (a4 == 2) ? Vh : Vl;
    kvsrc += (size_t)bh * S_ * DK_;
    const uint32_t kvdst = s0 + (uint32_t)a4 * 8192;

    {
        const __nv_bfloat16* g = kvsrc;
#pragma unroll
        for (int p = 0; p < 8; p++) {
            const int row = p * 8 + rs4;
            cpa16(kvdst + (uint32_t)row * 128 + (uint32_t)((ch4 ^ (row & 7)) << 4),
                  g + (size_t)row * 64 + ch4 * 8);
        }
    }
    CP_COMMIT();

    float m_i[2] = {-1e30f, -1e30f};
    float l_i[2] = {0.f, 0.f};
    float oac[8][4];
#pragma unroll
    for (int t = 0; t < 8; t++)
#pragma unroll
        for (int e = 0; e < 4; e++) oac[t][e] = 0.f;

    for (int jt = 0; jt < njt; jt++) {
        CP_WAIT0();
        __syncthreads();
        const uint32_t bb = s0 + (uint32_t)(jt & 1) * 32768;

        if (jt + 1 < njt) {
            const __nv_bfloat16* g = kvsrc + (size_t)(jt + 1) * 64 * 64;
            const uint32_t db = kvdst + (uint32_t)((jt + 1) & 1) * 32768;
#pragma unroll
            for (int p = 0; p < 8; p++) {
                const int row = p * 8 + rs4;
                cpa16(db + (uint32_t)row * 128 + (uint32_t)((ch4 ^ (row & 7)) << 4),
                      g + (size_t)row * 64 + ch4 * 8);
            }
            CP_COMMIT();
        }

        float sc[8][4];
#pragma unroll
        for (int t = 0; t < 8; t++)
#pragma unroll
            for (int e = 0; e < 4; e++) sc[t][e] = 0.f;

#pragma unroll
        for (int kk = 0; kk < 4; kk++) {
#pragma unroll
            for (int j = 0; j < 4; j++) {
                const int krow = 16 * j + (lane & 7) + ((lane & 16) >> 1);
                const uint32_t ka = bb + (uint32_t)krow * 128 +
                    (uint32_t)(((2 * kk + ((lane >> 3) & 1)) ^ (krow & 7)) << 4);
                uint32_t bhf[4], blf[4];
                ldsm4(bhf, ka);
                ldsm4(blf, ka + 8192);
                mma16816(sc[2 * j],     qfh[kk], bhf + 0);
                mma16816(sc[2 * j + 1], qfh[kk], bhf + 2);
                mma16816(sc[2 * j],     qfh[kk], blf + 0);
                mma16816(sc[2 * j + 1], qfh[kk], blf + 2);
                mma16816(sc[2 * j],     qfl[kk], bhf + 0);
                mma16816(sc[2 * j + 1], qfl[kk], bhf + 2);
            }
        }

        if (jt >= njt - 2) {
            const int kb = jt * 64;
#pragma unroll
            for (int t = 0; t < 8; t++)
#pragma unroll
                for (int e = 0; e < 4; e++) {
                    const int kg = kb + t * 8 + 2 * (lane & 3) + (e & 1);
                    const int qg = qbase + rb + (lane >> 2) + (e >> 1) * 8;
                    if (kg > qg) sc[t][e] = -1e9f;
                }
        }

#pragma unroll
        for (int h = 0; h < 2; h++) {
            float mr = -1e30f;
#pragma unroll
            for (int t = 0; t < 8; t++)
                mr = fmaxf(mr, fmaxf(sc[t][2 * h], sc[t][2 * h + 1]));
            mr = fmaxf(mr, __shfl_xor_sync(0xffffffffu, mr, 1));
            mr = fmaxf(mr, __shfl_xor_sync(0xffffffffu, mr, 2));
            const float mn = fmaxf(m_i[h], mr);
            const float alpha = exp2f(m_i[h] - mn);
            m_i[h] = mn;
            float rs = 0.f;
#pragma unroll
            for (int t = 0; t < 8; t++) {
                sc[t][2 * h]     = exp2f(sc[t][2 * h] - mn);
                sc[t][2 * h + 1] = exp2f(sc[t][2 * h + 1] - mn);
                rs += sc[t][2 * h] + sc[t][2 * h + 1];
            }
            rs += __shfl_xor_sync(0xffffffffu, rs, 1);
            rs += __shfl_xor_sync(0xffffffffu, rs, 2);
            l_i[h] = l_i[h] * alpha + rs;
#pragma unroll
            for (int t = 0; t < 8; t++) {
                oac[t][2 * h]     *= alpha;
                oac[t][2 * h + 1] *= alpha;
            }
        }

#pragma unroll
        for (int kk = 0; kk < 4; kk++) {
            uint32_t pah[4], pal[4];
            split2(sc[2 * kk][0],     sc[2 * kk][1],     pah[0], pal[0]);
            split2(sc[2 * kk][2],     sc[2 * kk][3],     pah[1], pal[1]);
            split2(sc[2 * kk + 1][0], sc[2 * kk + 1][1], pah[2], pal[2]);
            split2(sc[2 * kk + 1][2], sc[2 * kk + 1][3], pah[3], pal[3]);

            const int vrow = 16 * kk + (lane & 15);
            const int vr7 = vrow & 7;
#pragma unroll
            for (int j = 0; j < 4; j++) {
                const uint32_t va = bb + 16384 + (uint32_t)vrow * 128 +
                    (uint32_t)(((2 * j + (lane >> 4)) ^ vr7) << 4);
                uint32_t vhf[4], vlf[4];
                ldsm4t(vhf, va);
                ldsm4t(vlf, va + 8192);
                mma16816(oac[2 * j],     pah, vhf + 0);
                mma16816(oac[2 * j + 1], pah, vhf + 2);
                mma16816(oac[2 * j],     pah, vlf + 0);
                mma16816(oac[2 * j + 1], pah, vlf + 2);
                mma16816(oac[2 * j],     pal, vhf + 0);
                mma16816(oac[2 * j + 1], pal, vhf + 2);
            }
        }
    }

    const int bb_ = bh >> 4, hh = bh & 15;
#pragma unroll
    for (int h = 0; h < 2; h++) {
        const float invl = 1.f / l_i[h];
        const int rg = qbase + rb + (lane >> 2) + 8 * h;
        const size_t mrow = (size_t)(bb_ * 2048 + rg) * 1024;
#pragma unroll
        for (int t = 0; t < 8; t++) {
            const float v0 = oac[t][2 * h] * invl;
            const float v1 = oac[t][2 * h + 1] * invl;
            const int col = hh * 64 + t * 8 + 2 * (lane & 3);
            uint32_t hi, lo;
            split2(v0, v1, hi, lo);
            *(uint32_t*)(Ohi + mrow + col) = hi;
            *(uint32_t*)(Olo + mrow + col) = lo;
        }
    }
}

// ---------------------------------------------------------------------------
extern "C" void kernel_launch(void* const* d_in, const int* in_sizes, int n_in,
                              void* d_out, int out_size)
{
    const float* x  = (const float*)d_in[0];
    const float* Wq = (const float*)d_in[2];
    const float* bq = (const float*)d_in[3];
    const float* Wk = (const float*)d_in[4];
    const float* bk = (const float*)d_in[5];
    const float* Wv = (const float*)d_in[6];
    const float* bv = (const float*)d_in[7];
    const float* Wo = (const float*)d_in[8];
    const float* bo = (const float*)d_in[9];

    __nv_bfloat16 *xh, *xl, *wth, *wtl, *qh, *ql, *kh, *kl, *vh, *vl;
    cudaGetSymbolAddress((void**)&xh, g_Xhi);
    cudaGetSymbolAddress((void**)&xl, g_Xlo);
    cudaGetSymbolAddress((void**)&wth, g_Wth);
    cudaGetSymbolAddress((void**)&wtl, g_Wtl);
    cudaGetSymbolAddress((void**)&qh, g_Qh);
    cudaGetSymbolAddress((void**)&ql, g_Ql);
    cudaGetSymbolAddress((void**)&kh, g_Kh);
    cudaGetSymbolAddress((void**)&kl, g_Kl);
    cudaGetSymbolAddress((void**)&vh, g_Vh);
    cudaGetSymbolAddress((void**)&vl, g_Vl);

    const int n4 = M_ROWS * D_ / 4;
    const dim3 tb(32, 32);

    cudaFuncSetAttribute(gemm_tc, cudaFuncAttributeMaxDynamicSharedMemorySize, GSMEM);
    cudaFuncSetAttribute(flash_attn_tc, cudaFuncAttributeMaxDynamicSharedMemorySize, 65536);

    // split X once
    split_bf16<<<(n4 + 255) / 256, 256>>>(x, xh, xl, n4);

    // transpose+split all three QKV weights in one launch
    transpose_split<<<dim3(32, 32, 3), tb>>>(Wq, Wk, Wv, wth, wtl);

    // fused QKV projection
    gemm_tc<<<dim3(24, 32), 256, GSMEM>>>(xh, xl, wth, wtl, bq, bk, bv,
                                          nullptr, qh, ql, kh, kl, vh, vl, 1);

    // tensor-core attention; writes ctx hi/lo into xh/xl
    flash_attn_tc<<<dim3(S_ / 128, BH_), 256, 65536>>>(qh, ql, kh, kl, vh, vl, xh, xl);

    // output projection
    transpose_split<<<dim3(32, 32, 1), tb>>>(Wo, Wo, Wo, wth, wtl);
    gemm_tc<<<dim3(8, 32), 256, GSMEM>>>(xh, xl, wth, wtl, bo, bo, bo,
                                         (float*)d_out, nullptr, nullptr,
                                         nullptr, nullptr, nullptr, nullptr, 0);
}

// round 6
// speedup vs baseline: 3.2528x; 1.0106x over previous
#include <cuda_runtime.h>
#include <cuda_bf16.h>
#include <cstdint>

#define B_   2
#define S_   2048
#define D_   1024
#define H_   16
#define DK_  64
#define BH_  (B_ * H_)
#define M_ROWS (B_ * S_)   // 4096

// Q pre-scale: log2(e) / sqrt(DK)  ->  softmax becomes exp2(s - m)
#define QSCALE 0.18033688011112042f

// ---------------- scratch (static device globals) ----------------
__device__ __nv_bfloat16 g_Xhi[M_ROWS * D_];
__device__ __nv_bfloat16 g_Xlo[M_ROWS * D_];
__device__ __nv_bfloat16 g_Wth[3 * D_ * D_];
__device__ __nv_bfloat16 g_Wtl[3 * D_ * D_];
__device__ __nv_bfloat16 g_Qh[BH_ * S_ * DK_];
__device__ __nv_bfloat16 g_Ql[BH_ * S_ * DK_];
__device__ __nv_bfloat16 g_Kh[BH_ * S_ * DK_];
__device__ __nv_bfloat16 g_Kl[BH_ * S_ * DK_];
__device__ __nv_bfloat16 g_Vh[BH_ * S_ * DK_];
__device__ __nv_bfloat16 g_Vl[BH_ * S_ * DK_];

// ---------------- helpers ----------------
__device__ __forceinline__ uint32_t smem_u32(const void* p) {
    uint32_t a;
    asm("{ .reg .u64 t; cvta.to.shared.u64 t, %1; cvt.u32.u64 %0, t; }" : "=r"(a) : "l"(p));
    return a;
}
__device__ __forceinline__ void ldsm4(uint32_t* r, uint32_t addr) {
    asm volatile("ldmatrix.sync.aligned.m8n8.x4.shared.b16 {%0,%1,%2,%3}, [%4];"
        : "=r"(r[0]), "=r"(r[1]), "=r"(r[2]), "=r"(r[3]) : "r"(addr));
}
__device__ __forceinline__ void ldsm4t(uint32_t* r, uint32_t addr) {
    asm volatile("ldmatrix.sync.aligned.m8n8.x4.trans.shared.b16 {%0,%1,%2,%3}, [%4];"
        : "=r"(r[0]), "=r"(r[1]), "=r"(r[2]), "=r"(r[3]) : "r"(addr));
}
__device__ __forceinline__ void mma16816(float* c, const uint32_t* a, const uint32_t* b) {
    asm volatile("mma.sync.aligned.m16n8k16.row.col.f32.bf16.bf16.f32 "
        "{%0,%1,%2,%3}, {%4,%5,%6,%7}, {%8,%9}, {%0,%1,%2,%3};"
        : "+f"(c[0]), "+f"(c[1]), "+f"(c[2]), "+f"(c[3])
        : "r"(a[0]), "r"(a[1]), "r"(a[2]), "r"(a[3]), "r"(b[0]), "r"(b[1]));
}
__device__ __forceinline__ void cpa16(uint32_t d, const void* g) {
    asm volatile("cp.async.cg.shared.global [%0], [%1], 16;" :: "r"(d), "l"(g));
}
#define CP_COMMIT() asm volatile("cp.async.commit_group;" ::: "memory")
#define CP_WAIT0()  asm volatile("cp.async.wait_group 0;" ::: "memory")
#define CP_WAIT1()  asm volatile("cp.async.wait_group 1;" ::: "memory")

__device__ __forceinline__ void split2(float a, float b, uint32_t& hi, uint32_t& lo) {
    __nv_bfloat16 ha = __float2bfloat16(a), hb = __float2bfloat16(b);
    __nv_bfloat16 la = __float2bfloat16(a - __bfloat162float(ha));
    __nv_bfloat16 lb = __float2bfloat16(b - __bfloat162float(hb));
    __nv_bfloat162 hp, lp;
    hp.x = ha; hp.y = hb; lp.x = la; lp.y = lb;
    hi = *(uint32_t*)&hp; lo = *(uint32_t*)&lp;
}

// ---------------------------------------------------------------------------
__global__ __launch_bounds__(256) void split_bf16(
    const float* __restrict__ src, __nv_bfloat16* __restrict__ hi,
    __nv_bfloat16* __restrict__ lo, int n4)
{
    int i = blockIdx.x * blockDim.x + threadIdx.x;
    if (i >= n4) return;
    float4 v = ((const float4*)src)[i];
    uint32_t h0, l0, h1, l1;
    split2(v.x, v.y, h0, l0);
    split2(v.z, v.w, h1, l1);
    uint2 hu = {h0, h1}, lu = {l0, l1};
    ((uint2*)hi)[i] = hu;
    ((uint2*)lo)[i] = lu;
}

// ---------------------------------------------------------------------------
__global__ void transpose_split(const float* __restrict__ W0,
                                const float* __restrict__ W1,
                                const float* __restrict__ W2,
                                __nv_bfloat16* __restrict__ hi,
                                __nv_bfloat16* __restrict__ lo)
{
    __shared__ float t[32][33];
    const float* W = (blockIdx.z == 0) ? W0 : (blockIdx.z == 1) ? W1 : W2;
    const int k = blockIdx.y * 32 + threadIdx.y;
    const int n = blockIdx.x * 32 + threadIdx.x;
    t[threadIdx.y][threadIdx.x] = W[(size_t)k * D_ + n];
    __syncthreads();
    const int nn = blockIdx.x * 32 + threadIdx.y + blockIdx.z * D_;
    const int kk = blockIdx.y * 32 + threadIdx.x;
    float v = t[threadIdx.x][threadIdx.y];
    __nv_bfloat16 h = __float2bfloat16(v);
    __nv_bfloat16 l = __float2bfloat16(v - __bfloat162float(h));
    hi[(size_t)nn * D_ + kk] = h;
    lo[(size_t)nn * D_ + kk] = l;
}

// ---------------------------------------------------------------------------
// HMMA GEMM, cp.async 3-stage pipeline, 3x bf16-split mma.sync.
// MMA passes reordered: acc reuse distance 16 (hides HMMA latency).
// One barrier per K-slab.
// ---------------------------------------------------------------------------
#define GROWB 80
#define SLABB (128 * GROWB)       // 10240
#define STAGEB (4 * SLABB)        // 40960
#define GSMEM (3 * STAGEB)        // 122880

__global__ __launch_bounds__(256) void gemm_tc(
    const __nv_bfloat16* __restrict__ Ah, const __nv_bfloat16* __restrict__ Al,
    const __nv_bfloat16* __restrict__ Bh, const __nv_bfloat16* __restrict__ Bl,
    const float* __restrict__ b0, const float* __restrict__ b1,
    const float* __restrict__ b2, float* __restrict__ Yf,
    __nv_bfloat16* __restrict__ Qh, __nv_bfloat16* __restrict__ Ql,
    __nv_bfloat16* __restrict__ Kh, __nv_bfloat16* __restrict__ Kl,
    __nv_bfloat16* __restrict__ Vh, __nv_bfloat16* __restrict__ Vl,
    int mode)
{
    extern __shared__ __align__(16) unsigned char dsm[];
    const uint32_t s0 = smem_u32(dsm);

    const int tid = threadIdx.x, wid = tid >> 5, lane = tid & 31;
    const int wm = wid >> 2, wn = wid & 3;
    const int bm = blockIdx.y * 128, bn = blockIdx.x * 128;

    const int a4 = tid >> 6, t4 = tid & 63;
    const __nv_bfloat16* gsrc =
        (a4 == 0) ? Ah : (a4 == 1) ? Al : (a4 == 2) ? Bh : Bl;
    gsrc += (size_t)((a4 < 2) ? bm : bn) * 1024;
    const uint32_t slab = s0 + (uint32_t)a4 * SLABB;

    const uint32_t aRow = (uint32_t)(wm * 64 + (lane & 15));
    const uint32_t aCol = (uint32_t)(lane >> 4) * 16;
    const uint32_t bRow0 = (uint32_t)(wn * 32 + ((lane >> 4) & 1) * 8 + (lane & 7));
    const uint32_t bKoff = (uint32_t)((lane >> 3) & 1) * 16;

    float acc[16][4];
#pragma unroll
    for (int i = 0; i < 16; i++)
#pragma unroll
        for (int j = 0; j < 4; j++) acc[i][j] = 0.f;

    auto issue = [&](int ks) {
        const uint32_t st = slab + (uint32_t)(ks % 3) * STAGEB;
        const __nv_bfloat16* g = gsrc + ks * 32;
#pragma unroll
        for (int p = 0; p < 8; p++) {
            const int idx = p * 64 + t4;
            const int row = idx >> 2, ch = idx & 3;
            cpa16(st + (uint32_t)row * GROWB + (uint32_t)ch * 16,
                  g + (size_t)row * 1024 + ch * 8);
        }
        CP_COMMIT();
    };

    issue(0);
    issue(1);

    for (int ks = 0; ks < 32; ks++) {
        if (ks == 31) { CP_WAIT0(); } else { CP_WAIT1(); }
        __syncthreads();
        if (ks + 2 < 32) issue(ks + 2);

        const uint32_t sb  = s0 + (uint32_t)(ks % 3) * STAGEB;
        const uint32_t SAh = sb, SAl = sb + SLABB;
        const uint32_t SBh = sb + 2 * SLABB, SBl = sb + 3 * SLABB;

#pragma unroll
        for (int h = 0; h < 2; h++) {
            uint32_t fAh[4][4], fAl[4][4], fBh[4][2], fBl[4][2];
#pragma unroll
            for (int mt = 0; mt < 4; mt++) {
                const uint32_t ra = (aRow + (uint32_t)(mt * 16)) * GROWB +
                                    (uint32_t)h * 32 + aCol;
                ldsm4(fAh[mt], SAh + ra);
                ldsm4(fAl[mt], SAl + ra);
            }
#pragma unroll
            for (int g = 0; g < 2; g++) {
                uint32_t r[4];
                ldsm4(r, SBh + (bRow0 + (uint32_t)(g * 16)) * GROWB +
                         (uint32_t)h * 32 + bKoff);
                fBh[g * 2][0] = r[0]; fBh[g * 2][1] = r[1];
                fBh[g * 2 + 1][0] = r[2]; fBh[g * 2 + 1][1] = r[3];
            }
#pragma unroll
            for (int g = 0; g < 2; g++) {
                uint32_t r[4];
                ldsm4(r, SBl + (bRow0 + (uint32_t)(g * 16)) * GROWB +
                         (uint32_t)h * 32 + bKoff);
                fBl[g * 2][0] = r[0]; fBl[g * 2][1] = r[1];
                fBl[g * 2 + 1][0] = r[2]; fBl[g * 2 + 1][1] = r[3];
            }
            // pass 1: Ah x Bh (acc reuse distance 16)
#pragma unroll
            for (int mt = 0; mt < 4; mt++)
#pragma unroll
                for (int nt = 0; nt < 4; nt++)
                    mma16816(acc[mt * 4 + nt], fAh[mt], fBh[nt]);
            // pass 2: Al x Bh
#pragma unroll
            for (int mt = 0; mt < 4; mt++)
#pragma unroll
                for (int nt = 0; nt < 4; nt++)
                    mma16816(acc[mt * 4 + nt], fAl[mt], fBh[nt]);
            // pass 3: Ah x Bl
#pragma unroll
            for (int mt = 0; mt < 4; mt++)
#pragma unroll
                for (int nt = 0; nt < 4; nt++)
                    mma16816(acc[mt * 4 + nt], fAh[mt], fBl[nt]);
        }
    }

    // ---- epilogue ----
    const int qr = lane >> 2, qc = (lane & 3) * 2;
    const int proj = bn >> 10;
    const float* bias = (proj == 0) ? b0 : (proj == 1) ? b1 : b2;
    const float scale = (mode == 1 && proj == 0) ? QSCALE : 1.0f;
    __nv_bfloat16* Yh = (proj == 0) ? Qh : (proj == 1) ? Kh : Vh;
    __nv_bfloat16* Yl = (proj == 0) ? Ql : (proj == 1) ? Kl : Vl;
    const int bnl = bn & 1023;

#pragma unroll
    for (int mt = 0; mt < 4; mt++) {
#pragma unroll
        for (int nt = 0; nt < 4; nt++) {
            const float* a4p = acc[mt * 4 + nt];
            const int r0 = bm + wm * 64 + mt * 16 + qr;
            const int cn = bnl + wn * 32 + nt * 8 + qc;
            const float bv0 = bias[cn], bv1 = bias[cn + 1];
            if (mode == 0) {
                float2 v0 = {a4p[0] + bv0, a4p[1] + bv1};
                float2 v1 = {a4p[2] + bv0, a4p[3] + bv1};
                *(float2*)(Yf + (size_t)r0 * 1024 + cn) = v0;
                *(float2*)(Yf + (size_t)(r0 + 8) * 1024 + cn) = v1;
            } else {
                const float w0 = (a4p[0] + bv0) * scale, w1 = (a4p[1] + bv1) * scale;
                const float w2 = (a4p[2] + bv0) * scale, w3 = (a4p[3] + bv1) * scale;
                const int h  = cn >> 6, dk = cn & 63;
                const int b0i = r0 >> 11, s0i = r0 & 2047;
                const int b1i = (r0 + 8) >> 11, s1i = (r0 + 8) & 2047;
                const size_t o0 = (((size_t)(b0i * H_ + h)) * S_ + s0i) * DK_ + dk;
                const size_t o1 = (((size_t)(b1i * H_ + h)) * S_ + s1i) * DK_ + dk;
                uint32_t h0, l0, h1, l1;
                split2(w0, w1, h0, l0);
                split2(w2, w3, h1, l1);
                *(uint32_t*)(Yh + o0) = h0; *(uint32_t*)(Yl + o0) = l0;
                *(uint32_t*)(Yh + o1) = h1; *(uint32_t*)(Yl + o1) = l1;
            }
        }
    }
}

// ---------------------------------------------------------------------------
// Tensor-core flash attention (causal). MMA passes reordered for latency
// hiding; K/V fragments hoisted per kk.
// ---------------------------------------------------------------------------
__global__ __launch_bounds__(256, 1) void flash_attn_tc(
    const __nv_bfloat16* __restrict__ Qh, const __nv_bfloat16* __restrict__ Ql,
    const __nv_bfloat16* __restrict__ Kh, const __nv_bfloat16* __restrict__ Kl,
    const __nv_bfloat16* __restrict__ Vh, const __nv_bfloat16* __restrict__ Vl,
    __nv_bfloat16* __restrict__ Ohi, __nv_bfloat16* __restrict__ Olo)
{
    extern __shared__ __align__(16) unsigned char sm[];
    const uint32_t s0 = smem_u32(sm);

    const int tid = threadIdx.x, wid = tid >> 5, lane = tid & 31;
    const int qt = 15 - blockIdx.x;
    const int bh = blockIdx.y;
    const int qbase = qt * 128;
    const int njt = 2 * (qt + 1);
    const int rb = wid * 16;

    {
        const int arr = tid >> 7;
        const int t2 = tid & 127;
        const int rsub = t2 >> 3;
        const int ch = t2 & 7;
        const __nv_bfloat16* base = (arr ? Ql : Qh) + ((size_t)bh * S_ + qbase) * DK_;
        const uint32_t db = (uint32_t)arr * 16384;
#pragma unroll
        for (int p = 0; p < 8; p++) {
            const int row = p * 16 + rsub;
            *(uint4*)(sm + db + (uint32_t)row * 128 + (uint32_t)((ch ^ (row & 7)) << 4)) =
                *(const uint4*)(base + (size_t)row * 64 + ch * 8);
        }
    }
    __syncthreads();

    uint32_t qfh[4][4], qfl[4][4];
    {
        const int row = rb + (lane & 15);
        const int r7 = row & 7;
#pragma unroll
        for (int kk = 0; kk < 4; kk++) {
            const uint32_t a = s0 + (uint32_t)row * 128 +
                (uint32_t)(((2 * kk + (lane >> 4)) ^ r7) << 4);
            ldsm4(qfh[kk], a);
            ldsm4(qfl[kk], a + 16384);
        }
    }
    __syncthreads();

    const int a4  = tid >> 6;
    const int t4  = tid & 63;
    const int rs4 = t4 >> 3;
    const int ch4 = t4 & 7;
    const __nv_bfloat16* kvsrc =
        (a4 == 0) ? Kh : (a4 == 1) ? Kl : (a4 == 2) ? Vh : Vl;
    kvsrc += (size_t)bh * S_ * DK_;
    const uint32_t kvdst = s0 + (uint32_t)a4 * 8192;

    {
        const __nv_bfloat16* g = kvsrc;
#pragma unroll
        for (int p = 0; p < 8; p++) {
            const int row = p * 8 + rs4;
            cpa16(kvdst + (uint32_t)row * 128 + (uint32_t)((ch4 ^ (row & 7)) << 4),
                  g + (size_t)row * 64 + ch4 * 8);
        }
    }
    CP_COMMIT();

    float m_i[2] = {-1e30f, -1e30f};
    float l_i[2] = {0.f, 0.f};
    float oac[8][4];
#pragma unroll
    for (int t = 0; t < 8; t++)
#pragma unroll
        for (int e = 0; e < 4; e++) oac[t][e] = 0.f;

    for (int jt = 0; jt < njt; jt++) {
        CP_WAIT0();
        __syncthreads();
        const uint32_t bb = s0 + (uint32_t)(jt & 1) * 32768;

        if (jt + 1 < njt) {
            const __nv_bfloat16* g = kvsrc + (size_t)(jt + 1) * 64 * 64;
            const uint32_t db = kvdst + (uint32_t)((jt + 1) & 1) * 32768;
#pragma unroll
            for (int p = 0; p < 8; p++) {
                const int row = p * 8 + rs4;
                cpa16(db + (uint32_t)row * 128 + (uint32_t)((ch4 ^ (row & 7)) << 4),
                      g + (size_t)row * 64 + ch4 * 8);
            }
            CP_COMMIT();
        }

        float sc[8][4];
#pragma unroll
        for (int t = 0; t < 8; t++)
#pragma unroll
            for (int e = 0; e < 4; e++) sc[t][e] = 0.f;

        // ---- scores: hoist K frags per kk, 3 ordered passes ----
#pragma unroll
        for (int kk = 0; kk < 4; kk++) {
            uint32_t bhf[4][4], blf[4][4];
#pragma unroll
            for (int j = 0; j < 4; j++) {
                const int krow = 16 * j + (lane & 7) + ((lane & 16) >> 1);
                const uint32_t ka = bb + (uint32_t)krow * 128 +
                    (uint32_t)(((2 * kk + ((lane >> 3) & 1)) ^ (krow & 7)) << 4);
                ldsm4(bhf[j], ka);
                ldsm4(blf[j], ka + 8192);
            }
#pragma unroll
            for (int j = 0; j < 4; j++) {
                mma16816(sc[2 * j],     qfh[kk], bhf[j] + 0);
                mma16816(sc[2 * j + 1], qfh[kk], bhf[j] + 2);
            }
#pragma unroll
            for (int j = 0; j < 4; j++) {
                mma16816(sc[2 * j],     qfl[kk], bhf[j] + 0);
                mma16816(sc[2 * j + 1], qfl[kk], bhf[j] + 2);
            }
#pragma unroll
            for (int j = 0; j < 4; j++) {
                mma16816(sc[2 * j],     qfh[kk], blf[j] + 0);
                mma16816(sc[2 * j + 1], qfh[kk], blf[j] + 2);
            }
        }

        if (jt >= njt - 2) {
            const int kb = jt * 64;
#pragma unroll
            for (int t = 0; t < 8; t++)
#pragma unroll
                for (int e = 0; e < 4; e++) {
                    const int kg = kb + t * 8 + 2 * (lane & 3) + (e & 1);
                    const int qg = qbase + rb + (lane >> 2) + (e >> 1) * 8;
                    if (kg > qg) sc[t][e] = -1e9f;
                }
        }

#pragma unroll
        for (int h = 0; h < 2; h++) {
            float mr = -1e30f;
#pragma unroll
            for (int t = 0; t < 8; t++)
                mr = fmaxf(mr, fmaxf(sc[t][2 * h], sc[t][2 * h + 1]));
            mr = fmaxf(mr, __shfl_xor_sync(0xffffffffu, mr, 1));
            mr = fmaxf(mr, __shfl_xor_sync(0xffffffffu, mr, 2));
            const float mn = fmaxf(m_i[h], mr);
            const float alpha = exp2f(m_i[h] - mn);
            m_i[h] = mn;
            float rs = 0.f;
#pragma unroll
            for (int t = 0; t < 8; t++) {
                sc[t][2 * h]     = exp2f(sc[t][2 * h] - mn);
                sc[t][2 * h + 1] = exp2f(sc[t][2 * h + 1] - mn);
                rs += sc[t][2 * h] + sc[t][2 * h + 1];
            }
            rs += __shfl_xor_sync(0xffffffffu, rs, 1);
            rs += __shfl_xor_sync(0xffffffffu, rs, 2);
            l_i[h] = l_i[h] * alpha + rs;
#pragma unroll
            for (int t = 0; t < 8; t++) {
                oac[t][2 * h]     *= alpha;
                oac[t][2 * h + 1] *= alpha;
            }
        }

        // ---- PV: hoist V frags per kk, 3 ordered passes ----
#pragma unroll
        for (int kk = 0; kk < 4; kk++) {
            uint32_t pah[4], pal[4];
            split2(sc[2 * kk][0],     sc[2 * kk][1],     pah[0], pal[0]);
            split2(sc[2 * kk][2],     sc[2 * kk][3],     pah[1], pal[1]);
            split2(sc[2 * kk + 1][0], sc[2 * kk + 1][1], pah[2], pal[2]);
            split2(sc[2 * kk + 1][2], sc[2 * kk + 1][3], pah[3], pal[3]);

            const int vrow = 16 * kk + (lane & 15);
            const int vr7 = vrow & 7;
            uint32_t vhf[4][4], vlf[4][4];
#pragma unroll
            for (int j = 0; j < 4; j++) {
                const uint32_t va = bb + 16384 + (uint32_t)vrow * 128 +
                    (uint32_t)(((2 * j + (lane >> 4)) ^ vr7) << 4);
                ldsm4t(vhf[j], va);
                ldsm4t(vlf[j], va + 8192);
            }
#pragma unroll
            for (int j = 0; j < 4; j++) {
                mma16816(oac[2 * j],     pah, vhf[j] + 0);
                mma16816(oac[2 * j + 1], pah, vhf[j] + 2);
            }
#pragma unroll
            for (int j = 0; j < 4; j++) {
                mma16816(oac[2 * j],     pal, vhf[j] + 0);
                mma16816(oac[2 * j + 1], pal, vhf[j] + 2);
            }
#pragma unroll
            for (int j = 0; j < 4; j++) {
                mma16816(oac[2 * j],     pah, vlf[j] + 0);
                mma16816(oac[2 * j + 1], pah, vlf[j] + 2);
            }
        }
    }

    const int bb_ = bh >> 4, hh = bh & 15;
#pragma unroll
    for (int h = 0; h < 2; h++) {
        const float invl = 1.f / l_i[h];
        const int rg = qbase + rb + (lane >> 2) + 8 * h;
        const size_t mrow = (size_t)(bb_ * 2048 + rg) * 1024;
#pragma unroll
        for (int t = 0; t < 8; t++) {
            const float v0 = oac[t][2 * h] * invl;
            const float v1 = oac[t][2 * h + 1] * invl;
            const int col = hh * 64 + t * 8 + 2 * (lane & 3);
            uint32_t hi, lo;
            split2(v0, v1, hi, lo);
            *(uint32_t*)(Ohi + mrow + col) = hi;
            *(uint32_t*)(Olo + mrow + col) = lo;
        }
    }
}

// ---------------------------------------------------------------------------
extern "C" void kernel_launch(void* const* d_in, const int* in_sizes, int n_in,
                              void* d_out, int out_size)
{
    const float* x  = (const float*)d_in[0];
    const float* Wq = (const float*)d_in[2];
    const float* bq = (const float*)d_in[3];
    const float* Wk = (const float*)d_in[4];
    const float* bk = (const float*)d_in[5];
    const float* Wv = (const float*)d_in[6];
    const float* bv = (const float*)d_in[7];
    const float* Wo = (const float*)d_in[8];
    const float* bo = (const float*)d_in[9];

    __nv_bfloat16 *xh, *xl, *wth, *wtl, *qh, *ql, *kh, *kl, *vh, *vl;
    cudaGetSymbolAddress((void**)&xh, g_Xhi);
    cudaGetSymbolAddress((void**)&xl, g_Xlo);
    cudaGetSymbolAddress((void**)&wth, g_Wth);
    cudaGetSymbolAddress((void**)&wtl, g_Wtl);
    cudaGetSymbolAddress((void**)&qh, g_Qh);
    cudaGetSymbolAddress((void**)&ql, g_Ql);
    cudaGetSymbolAddress((void**)&kh, g_Kh);
    cudaGetSymbolAddress((void**)&kl, g_Kl);
    cudaGetSymbolAddress((void**)&vh, g_Vh);
    cudaGetSymbolAddress((void**)&vl, g_Vl);

    const int n4 = M_ROWS * D_ / 4;
    const dim3 tb(32, 32);

    cudaFuncSetAttribute(gemm_tc, cudaFuncAttributeMaxDynamicSharedMemorySize, GSMEM);
    cudaFuncSetAttribute(flash_attn_tc, cudaFuncAttributeMaxDynamicSharedMemorySize, 65536);

    split_bf16<<<(n4 + 255) / 256, 256>>>(x, xh, xl, n4);
    transpose_split<<<dim3(32, 32, 3), tb>>>(Wq, Wk, Wv, wth, wtl);

    gemm_tc<<<dim3(24, 32), 256, GSMEM>>>(xh, xl, wth, wtl, bq, bk, bv,
                                          nullptr, qh, ql, kh, kl, vh, vl, 1);

    flash_attn_tc<<<dim3(S_ / 128, BH_), 256, 65536>>>(qh, ql, kh, kl, vh, vl, xh, xl);

    transpose_split<<<dim3(32, 32, 1), tb>>>(Wo, Wo, Wo, wth, wtl);
    gemm_tc<<<dim3(8, 32), 256, GSMEM>>>(xh, xl, wth, wtl, bo, bo, bo,
                                         (float*)d_out, nullptr, nullptr,
                                         nullptr, nullptr, nullptr, nullptr, 0);
}

// round 7
// speedup vs baseline: 3.7027x; 1.1383x over previous
#include <cuda_runtime.h>
#include <cuda_bf16.h>
#include <cstdint>

#define B_   2
#define S_   2048
#define D_   1024
#define H_   16
#define DK_  64
#define BH_  (B_ * H_)
#define M_ROWS (B_ * S_)   // 4096

#define QSCALE 0.18033688011112042f   // log2(e)/sqrt(64)

// ---------------- scratch ----------------
__device__ __nv_bfloat16 g_Xhi[M_ROWS * D_];
__device__ __nv_bfloat16 g_Xlo[M_ROWS * D_];
__device__ __nv_bfloat16 g_Wth[3 * D_ * D_];
__device__ __nv_bfloat16 g_Wtl[3 * D_ * D_];
__device__ __nv_bfloat16 g_Qh[BH_ * S_ * DK_];
__device__ __nv_bfloat16 g_Ql[BH_ * S_ * DK_];
__device__ __nv_bfloat16 g_Kh[BH_ * S_ * DK_];
__device__ __nv_bfloat16 g_Kl[BH_ * S_ * DK_];
__device__ __nv_bfloat16 g_Vh[BH_ * S_ * DK_];
__device__ __nv_bfloat16 g_Vl[BH_ * S_ * DK_];

// ---------------- helpers ----------------
__device__ __forceinline__ uint32_t smem_u32(const void* p) {
    uint32_t a;
    asm("{ .reg .u64 t; cvta.to.shared.u64 t, %1; cvt.u32.u64 %0, t; }" : "=r"(a) : "l"(p));
    return a;
}
__device__ __forceinline__ void ldsm4(uint32_t* r, uint32_t addr) {
    asm volatile("ldmatrix.sync.aligned.m8n8.x4.shared.b16 {%0,%1,%2,%3}, [%4];"
        : "=r"(r[0]), "=r"(r[1]), "=r"(r[2]), "=r"(r[3]) : "r"(addr));
}
__device__ __forceinline__ void ldsm4t(uint32_t* r, uint32_t addr) {
    asm volatile("ldmatrix.sync.aligned.m8n8.x4.trans.shared.b16 {%0,%1,%2,%3}, [%4];"
        : "=r"(r[0]), "=r"(r[1]), "=r"(r[2]), "=r"(r[3]) : "r"(addr));
}
__device__ __forceinline__ void mma16816(float* c, const uint32_t* a, const uint32_t* b) {
    asm volatile("mma.sync.aligned.m16n8k16.row.col.f32.bf16.bf16.f32 "
        "{%0,%1,%2,%3}, {%4,%5,%6,%7}, {%8,%9}, {%0,%1,%2,%3};"
        : "+f"(c[0]), "+f"(c[1]), "+f"(c[2]), "+f"(c[3])
        : "r"(a[0]), "r"(a[1]), "r"(a[2]), "r"(a[3]), "r"(b[0]), "r"(b[1]));
}
__device__ __forceinline__ void cpa16(uint32_t d, const void* g) {
    asm volatile("cp.async.cg.shared.global [%0], [%1], 16;" :: "r"(d), "l"(g));
}
#define CP_COMMIT() asm volatile("cp.async.commit_group;" ::: "memory")
#define CP_WAIT0()  asm volatile("cp.async.wait_group 0;" ::: "memory")

__device__ __forceinline__ void split2(float a, float b, uint32_t& hi, uint32_t& lo) {
    __nv_bfloat16 ha = __float2bfloat16(a), hb = __float2bfloat16(b);
    __nv_bfloat16 la = __float2bfloat16(a - __bfloat162float(ha));
    __nv_bfloat16 lb = __float2bfloat16(b - __bfloat162float(hb));
    __nv_bfloat162 hp, lp;
    hp.x = ha; hp.y = hb; lp.x = la; lp.y = lb;
    hi = *(uint32_t*)&hp; lo = *(uint32_t*)&lp;
}

// ---------------------------------------------------------------------------
__global__ __launch_bounds__(256) void split_bf16(
    const float* __restrict__ src, __nv_bfloat16* __restrict__ hi,
    __nv_bfloat16* __restrict__ lo, int n4)
{
    int i = blockIdx.x * blockDim.x + threadIdx.x;
    if (i >= n4) return;
    float4 v = ((const float4*)src)[i];
    uint32_t h0, l0, h1, l1;
    split2(v.x, v.y, h0, l0);
    split2(v.z, v.w, h1, l1);
    uint2 hu = {h0, h1}, lu = {l0, l1};
    ((uint2*)hi)[i] = hu;
    ((uint2*)lo)[i] = lu;
}

// ---------------------------------------------------------------------------
__global__ void transpose_split(const float* __restrict__ W0,
                                const float* __restrict__ W1,
                                const float* __restrict__ W2,
                                __nv_bfloat16* __restrict__ hi,
                                __nv_bfloat16* __restrict__ lo)
{
    __shared__ float t[32][33];
    const float* W = (blockIdx.z == 0) ? W0 : (blockIdx.z == 1) ? W1 : W2;
    const int k = blockIdx.y * 32 + threadIdx.y;
    const int n = blockIdx.x * 32 + threadIdx.x;
    t[threadIdx.y][threadIdx.x] = W[(size_t)k * D_ + n];
    __syncthreads();
    const int nn = blockIdx.x * 32 + threadIdx.y + blockIdx.z * D_;
    const int kk = blockIdx.y * 32 + threadIdx.x;
    float v = t[threadIdx.x][threadIdx.y];
    __nv_bfloat16 h = __float2bfloat16(v);
    __nv_bfloat16 l = __float2bfloat16(v - __bfloat162float(h));
    hi[(size_t)nn * D_ + kk] = h;
    lo[(size_t)nn * D_ + kk] = l;
}

// ---------------------------------------------------------------------------
// HMMA GEMM: 2-stage cp.async prefetch-1, single barrier per slab, 2 CTAs/SM.
// 128x128 tile, BK=32, 3x bf16-split mma.sync.
// ---------------------------------------------------------------------------
#define GROWB 80
#define SLABB (128 * GROWB)       // 10240
#define STAGEB (4 * SLABB)        // 40960
#define GSMEM (2 * STAGEB)        // 81920

__global__ __launch_bounds__(256, 2) void gemm_tc(
    const __nv_bfloat16* __restrict__ Ah, const __nv_bfloat16* __restrict__ Al,
    const __nv_bfloat16* __restrict__ Bh, const __nv_bfloat16* __restrict__ Bl,
    const float* __restrict__ b0, const float* __restrict__ b1,
    const float* __restrict__ b2, float* __restrict__ Yf,
    __nv_bfloat16* __restrict__ Qh, __nv_bfloat16* __restrict__ Ql,
    __nv_bfloat16* __restrict__ Kh, __nv_bfloat16* __restrict__ Kl,
    __nv_bfloat16* __restrict__ Vh, __nv_bfloat16* __restrict__ Vl,
    int mode)
{
    extern __shared__ __align__(16) unsigned char dsm[];
    const uint32_t s0 = smem_u32(dsm);

    const int tid = threadIdx.x, wid = tid >> 5, lane = tid & 31;
    const int wm = wid >> 2, wn = wid & 3;
    const int bm = blockIdx.y * 128, bn = blockIdx.x * 128;

    const int a4 = tid >> 6, t4 = tid & 63;
    const __nv_bfloat16* gsrc =
        (a4 == 0) ? Ah : (a4 == 1) ? Al : (a4 == 2) ? Bh : Bl;
    gsrc += (size_t)((a4 < 2) ? bm : bn) * 1024;
    const uint32_t slab = s0 + (uint32_t)a4 * SLABB;

    const uint32_t aRow = (uint32_t)(wm * 64 + (lane & 15));
    const uint32_t aCol = (uint32_t)(lane >> 4) * 16;
    const uint32_t bRow0 = (uint32_t)(wn * 32 + ((lane >> 4) & 1) * 8 + (lane & 7));
    const uint32_t bKoff = (uint32_t)((lane >> 3) & 1) * 16;

    float acc[16][4];
#pragma unroll
    for (int i = 0; i < 16; i++)
#pragma unroll
        for (int j = 0; j < 4; j++) acc[i][j] = 0.f;

    auto issue = [&](int ks) {
        const uint32_t st = slab + (uint32_t)(ks & 1) * STAGEB;
        const __nv_bfloat16* g = gsrc + ks * 32;
#pragma unroll
        for (int p = 0; p < 8; p++) {
            const int idx = p * 64 + t4;
            const int row = idx >> 2, ch = idx & 3;
            cpa16(st + (uint32_t)row * GROWB + (uint32_t)ch * 16,
                  g + (size_t)row * 1024 + ch * 8);
        }
        CP_COMMIT();
    };

    issue(0);

    for (int ks = 0; ks < 32; ks++) {
        CP_WAIT0();
        __syncthreads();              // stage ks ready; all warps done ks-1
        if (ks + 1 < 32) issue(ks + 1);

        const uint32_t sb  = s0 + (uint32_t)(ks & 1) * STAGEB;
        const uint32_t SAh = sb, SAl = sb + SLABB;
        const uint32_t SBh = sb + 2 * SLABB, SBl = sb + 3 * SLABB;

#pragma unroll
        for (int h = 0; h < 2; h++) {
            uint32_t fA[4][4], fA2[4][4], fB[4][2];
            // A hi + B hi
#pragma unroll
            for (int mt = 0; mt < 4; mt++)
                ldsm4(fA[mt], SAh + (aRow + (uint32_t)(mt * 16)) * GROWB +
                              (uint32_t)h * 32 + aCol);
#pragma unroll
            for (int g = 0; g < 2; g++) {
                uint32_t r[4];
                ldsm4(r, SBh + (bRow0 + (uint32_t)(g * 16)) * GROWB +
                         (uint32_t)h * 32 + bKoff);
                fB[g * 2][0] = r[0]; fB[g * 2][1] = r[1];
                fB[g * 2 + 1][0] = r[2]; fB[g * 2 + 1][1] = r[3];
            }
            // pass 1: Ah x Bh
#pragma unroll
            for (int mt = 0; mt < 4; mt++)
#pragma unroll
                for (int nt = 0; nt < 4; nt++)
                    mma16816(acc[mt * 4 + nt], fA[mt], fB[nt]);
            // A lo
#pragma unroll
            for (int mt = 0; mt < 4; mt++)
                ldsm4(fA2[mt], SAl + (aRow + (uint32_t)(mt * 16)) * GROWB +
                               (uint32_t)h * 32 + aCol);
            // pass 2: Al x Bh
#pragma unroll
            for (int mt = 0; mt < 4; mt++)
#pragma unroll
                for (int nt = 0; nt < 4; nt++)
                    mma16816(acc[mt * 4 + nt], fA2[mt], fB[nt]);
            // B lo (overwrite fB)
#pragma unroll
            for (int g = 0; g < 2; g++) {
                uint32_t r[4];
                ldsm4(r, SBl + (bRow0 + (uint32_t)(g * 16)) * GROWB +
                         (uint32_t)h * 32 + bKoff);
                fB[g * 2][0] = r[0]; fB[g * 2][1] = r[1];
                fB[g * 2 + 1][0] = r[2]; fB[g * 2 + 1][1] = r[3];
            }
            // pass 3: Ah x Bl
#pragma unroll
            for (int mt = 0; mt < 4; mt++)
#pragma unroll
                for (int nt = 0; nt < 4; nt++)
                    mma16816(acc[mt * 4 + nt], fA[mt], fB[nt]);
        }
    }

    // ---- epilogue ----
    const int qr = lane >> 2, qc = (lane & 3) * 2;
    const int proj = bn >> 10;
    const float* bias = (proj == 0) ? b0 : (proj == 1) ? b1 : b2;
    const float scale = (mode == 1 && proj == 0) ? QSCALE : 1.0f;
    __nv_bfloat16* Yh = (proj == 0) ? Qh : (proj == 1) ? Kh : Vh;
    __nv_bfloat16* Yl = (proj == 0) ? Ql : (proj == 1) ? Kl : Vl;
    const int bnl = bn & 1023;

#pragma unroll
    for (int mt = 0; mt < 4; mt++) {
#pragma unroll
        for (int nt = 0; nt < 4; nt++) {
            const float* a4p = acc[mt * 4 + nt];
            const int r0 = bm + wm * 64 + mt * 16 + qr;
            const int cn = bnl + wn * 32 + nt * 8 + qc;
            const float bv0 = bias[cn], bv1 = bias[cn + 1];
            if (mode == 0) {
                float2 v0 = {a4p[0] + bv0, a4p[1] + bv1};
                float2 v1 = {a4p[2] + bv0, a4p[3] + bv1};
                *(float2*)(Yf + (size_t)r0 * 1024 + cn) = v0;
                *(float2*)(Yf + (size_t)(r0 + 8) * 1024 + cn) = v1;
            } else {
                const float w0 = (a4p[0] + bv0) * scale, w1 = (a4p[1] + bv1) * scale;
                const float w2 = (a4p[2] + bv0) * scale, w3 = (a4p[3] + bv1) * scale;
                const int h  = cn >> 6, dk = cn & 63;
                const int b0i = r0 >> 11, s0i = r0 & 2047;
                const int b1i = (r0 + 8) >> 11, s1i = (r0 + 8) & 2047;
                const size_t o0 = (((size_t)(b0i * H_ + h)) * S_ + s0i) * DK_ + dk;
                const size_t o1 = (((size_t)(b1i * H_ + h)) * S_ + s1i) * DK_ + dk;
                uint32_t h0, l0, h1, l1;
                split2(w0, w1, h0, l0);
                split2(w2, w3, h1, l1);
                *(uint32_t*)(Yh + o0) = h0; *(uint32_t*)(Yl + o0) = l0;
                *(uint32_t*)(Yh + o1) = h1; *(uint32_t*)(Yl + o1) = l1;
            }
        }
    }
}

// ---------------------------------------------------------------------------
// Flash attention (causal): 128 threads / 64 q-rows per CTA, 2 CTAs/SM.
// smem 80KB: Qh@0, Ql@8192; KV stages at 16384 + st*32768:
//   Kh+0, Kl+8192, Vh+16384, Vl+24576.
// ---------------------------------------------------------------------------
#define ASMEM 81920

__global__ __launch_bounds__(128, 2) void flash_attn_tc(
    const __nv_bfloat16* __restrict__ Qh, const __nv_bfloat16* __restrict__ Ql,
    const __nv_bfloat16* __restrict__ Kh, const __nv_bfloat16* __restrict__ Kl,
    const __nv_bfloat16* __restrict__ Vh, const __nv_bfloat16* __restrict__ Vl,
    __nv_bfloat16* __restrict__ Ohi, __nv_bfloat16* __restrict__ Olo)
{
    extern __shared__ __align__(16) unsigned char sm[];
    const uint32_t s0 = smem_u32(sm);

    const int tid = threadIdx.x, wid = tid >> 5, lane = tid & 31;
    const int qt = 31 - blockIdx.x;          // heavy tiles first
    const int bh = blockIdx.y;
    const int qbase = qt * 64;
    const int njt = qt + 1;
    const int rb = wid * 16;                 // warp q-row base (0..48)

    // ---- stage Q (64 rows) ----
    {
        const int arr = tid >> 6;            // 0=hi 1=lo
        const int t2 = tid & 63;
        const __nv_bfloat16* base = (arr ? Ql : Qh) + ((size_t)bh * S_ + qbase) * DK_;
        const uint32_t db = (uint32_t)arr * 8192;
#pragma unroll
        for (int p = 0; p < 8; p++) {
            const int idx = p * 64 + t2;
            const int row = idx >> 3, ch = idx & 7;
            *(uint4*)(sm + db + (uint32_t)row * 128 + (uint32_t)((ch ^ (row & 7)) << 4)) =
                *(const uint4*)(base + (size_t)row * 64 + ch * 8);
        }
    }
    __syncthreads();

    uint32_t qfh[4][4], qfl[4][4];
    {
        const int row = rb + (lane & 15);
        const int r7 = row & 7;
#pragma unroll
        for (int kk = 0; kk < 4; kk++) {
            const uint32_t a = s0 + (uint32_t)row * 128 +
                (uint32_t)(((2 * kk + (lane >> 4)) ^ r7) << 4);
            ldsm4(qfh[kk], a);
            ldsm4(qfl[kk], a + 8192);
        }
    }
    __syncthreads();

    // ---- KV copy geometry: 32 threads per array, 16x16B each ----
    const int a4  = tid >> 5;                // 0:Kh 1:Kl 2:Vh 3:Vl
    const int t5  = tid & 31;
    const __nv_bfloat16* kvsrc =
        (a4 == 0) ? Kh : (a4 == 1) ? Kl : (a4 == 2) ? Vh : Vl;
    kvsrc += (size_t)bh * S_ * DK_;
    const uint32_t kvdst = s0 + 16384 + (uint32_t)a4 * 8192;

    {
        const __nv_bfloat16* g = kvsrc;
#pragma unroll
        for (int p = 0; p < 16; p++) {
            const int idx = p * 32 + t5;
            const int row = idx >> 3, ch = idx & 7;
            cpa16(kvdst + (uint32_t)row * 128 + (uint32_t)((ch ^ (row & 7)) << 4),
                  g + (size_t)row * 64 + ch * 8);
        }
    }
    CP_COMMIT();

    float m_i[2] = {-1e30f, -1e30f};
    float l_i[2] = {0.f, 0.f};
    float oac[8][4];
#pragma unroll
    for (int t = 0; t < 8; t++)
#pragma unroll
        for (int e = 0; e < 4; e++) oac[t][e] = 0.f;

    for (int jt = 0; jt < njt; jt++) {
        CP_WAIT0();
        __syncthreads();
        const uint32_t bb = s0 + 16384 + (uint32_t)(jt & 1) * 32768;

        if (jt + 1 < njt) {
            const __nv_bfloat16* g = kvsrc + (size_t)(jt + 1) * 64 * 64;
            const uint32_t db = kvdst + (uint32_t)((jt + 1) & 1) * 32768;
#pragma unroll
            for (int p = 0; p < 16; p++) {
                const int idx = p * 32 + t5;
                const int row = idx >> 3, ch = idx & 7;
                cpa16(db + (uint32_t)row * 128 + (uint32_t)((ch ^ (row & 7)) << 4),
                      g + (size_t)row * 64 + ch * 8);
            }
            CP_COMMIT();
        }

        float sc[8][4];
#pragma unroll
        for (int t = 0; t < 8; t++)
#pragma unroll
            for (int e = 0; e < 4; e++) sc[t][e] = 0.f;

#pragma unroll
        for (int kk = 0; kk < 4; kk++) {
#pragma unroll
            for (int j = 0; j < 4; j++) {
                const int krow = 16 * j + (lane & 7) + ((lane & 16) >> 1);
                const uint32_t ka = bb + (uint32_t)krow * 128 +
                    (uint32_t)(((2 * kk + ((lane >> 3) & 1)) ^ (krow & 7)) << 4);
                uint32_t bhf[4], blf[4];
                ldsm4(bhf, ka);
                ldsm4(blf, ka + 8192);
                mma16816(sc[2 * j],     qfh[kk], bhf + 0);
                mma16816(sc[2 * j + 1], qfh[kk], bhf + 2);
                mma16816(sc[2 * j],     qfh[kk], blf + 0);
                mma16816(sc[2 * j + 1], qfh[kk], blf + 2);
                mma16816(sc[2 * j],     qfl[kk], bhf + 0);
                mma16816(sc[2 * j + 1], qfl[kk], bhf + 2);
            }
        }

        if (jt == njt - 1) {   // diagonal tile
#pragma unroll
            for (int t = 0; t < 8; t++)
#pragma unroll
                for (int e = 0; e < 4; e++) {
                    const int kg = t * 8 + 2 * (lane & 3) + (e & 1);
                    const int qg = rb + (lane >> 2) + (e >> 1) * 8;
                    if (kg > qg) sc[t][e] = -1e9f;
                }
        }

#pragma unroll
        for (int h = 0; h < 2; h++) {
            float mr = -1e30f;
#pragma unroll
            for (int t = 0; t < 8; t++)
                mr = fmaxf(mr, fmaxf(sc[t][2 * h], sc[t][2 * h + 1]));
            mr = fmaxf(mr, __shfl_xor_sync(0xffffffffu, mr, 1));
            mr = fmaxf(mr, __shfl_xor_sync(0xffffffffu, mr, 2));
            const float mn = fmaxf(m_i[h], mr);
            const float alpha = exp2f(m_i[h] - mn);
            m_i[h] = mn;
            float rs = 0.f;
#pragma unroll
            for (int t = 0; t < 8; t++) {
                sc[t][2 * h]     = exp2f(sc[t][2 * h] - mn);
                sc[t][2 * h + 1] = exp2f(sc[t][2 * h + 1] - mn);
                rs += sc[t][2 * h] + sc[t][2 * h + 1];
            }
            rs += __shfl_xor_sync(0xffffffffu, rs, 1);
            rs += __shfl_xor_sync(0xffffffffu, rs, 2);
            l_i[h] = l_i[h] * alpha + rs;
#pragma unroll
            for (int t = 0; t < 8; t++) {
                oac[t][2 * h]     *= alpha;
                oac[t][2 * h + 1] *= alpha;
            }
        }

#pragma unroll
        for (int kk = 0; kk < 4; kk++) {
            uint32_t pah[4], pal[4];
            split2(sc[2 * kk][0],     sc[2 * kk][1],     pah[0], pal[0]);
            split2(sc[2 * kk][2],     sc[2 * kk][3],     pah[1], pal[1]);
            split2(sc[2 * kk + 1][0], sc[2 * kk + 1][1], pah[2], pal[2]);
            split2(sc[2 * kk + 1][2], sc[2 * kk + 1][3], pah[3], pal[3]);

            const int vrow = 16 * kk + (lane & 15);
            const int vr7 = vrow & 7;
#pragma unroll
            for (int j = 0; j < 4; j++) {
                const uint32_t va = bb + 16384 + (uint32_t)vrow * 128 +
                    (uint32_t)(((2 * j + (lane >> 4)) ^ vr7) << 4);
                uint32_t vhf[4], vlf[4];
                ldsm4t(vhf, va);
                ldsm4t(vlf, va + 8192);
                mma16816(oac[2 * j],     pah, vhf + 0);
                mma16816(oac[2 * j + 1], pah, vhf + 2);
                mma16816(oac[2 * j],     pah, vlf + 0);
                mma16816(oac[2 * j + 1], pah, vlf + 2);
                mma16816(oac[2 * j],     pal, vhf + 0);
                mma16816(oac[2 * j + 1], pal, vhf + 2);
            }
        }
    }

    const int bb_ = bh >> 4, hh = bh & 15;
#pragma unroll
    for (int h = 0; h < 2; h++) {
        const float invl = 1.f / l_i[h];
        const int rg = qbase + rb + (lane >> 2) + 8 * h;
        const size_t mrow = (size_t)(bb_ * 2048 + rg) * 1024;
#pragma unroll
        for (int t = 0; t < 8; t++) {
            const float v0 = oac[t][2 * h] * invl;
            const float v1 = oac[t][2 * h + 1] * invl;
            const int col = hh * 64 + t * 8 + 2 * (lane & 3);
            uint32_t hi, lo;
            split2(v0, v1, hi, lo);
            *(uint32_t*)(Ohi + mrow + col) = hi;
            *(uint32_t*)(Olo + mrow + col) = lo;
        }
    }
}

// ---------------------------------------------------------------------------
extern "C" void kernel_launch(void* const* d_in, const int* in_sizes, int n_in,
                              void* d_out, int out_size)
{
    const float* x  = (const float*)d_in[0];
    const float* Wq = (const float*)d_in[2];
    const float* bq = (const float*)d_in[3];
    const float* Wk = (const float*)d_in[4];
    const float* bk = (const float*)d_in[5];
    const float* Wv = (const float*)d_in[6];
    const float* bv = (const float*)d_in[7];
    const float* Wo = (const float*)d_in[8];
    const float* bo = (const float*)d_in[9];

    __nv_bfloat16 *xh, *xl, *wth, *wtl, *qh, *ql, *kh, *kl, *vh, *vl;
    cudaGetSymbolAddress((void**)&xh, g_Xhi);
    cudaGetSymbolAddress((void**)&xl, g_Xlo);
    cudaGetSymbolAddress((void**)&wth, g_Wth);
    cudaGetSymbolAddress((void**)&wtl, g_Wtl);
    cudaGetSymbolAddress((void**)&qh, g_Qh);
    cudaGetSymbolAddress((void**)&ql, g_Ql);
    cudaGetSymbolAddress((void**)&kh, g_Kh);
    cudaGetSymbolAddress((void**)&kl, g_Kl);
    cudaGetSymbolAddress((void**)&vh, g_Vh);
    cudaGetSymbolAddress((void**)&vl, g_Vl);

    const int n4 = M_ROWS * D_ / 4;
    const dim3 tb(32, 32);

    cudaFuncSetAttribute(gemm_tc, cudaFuncAttributeMaxDynamicSharedMemorySize, GSMEM);
    cudaFuncSetAttribute(flash_attn_tc, cudaFuncAttributeMaxDynamicSharedMemorySize, ASMEM);

    split_bf16<<<(n4 + 255) / 256, 256>>>(x, xh, xl, n4);
    transpose_split<<<dim3(32, 32, 3), tb>>>(Wq, Wk, Wv, wth, wtl);

    gemm_tc<<<dim3(24, 32), 256, GSMEM>>>(xh, xl, wth, wtl, bq, bk, bv,
                                          nullptr, qh, ql, kh, kl, vh, vl, 1);

    flash_attn_tc<<<dim3(32, BH_), 128, ASMEM>>>(qh, ql, kh, kl, vh, vl, xh, xl);

    transpose_split<<<dim3(32, 32, 1), tb>>>(Wo, Wo, Wo, wth, wtl);
    gemm_tc<<<dim3(8, 32), 256, GSMEM>>>(xh, xl, wth, wtl, bo, bo, bo,
                                         (float*)d_out, nullptr, nullptr,
                                         nullptr, nullptr, nullptr, nullptr, 0);
}